// round 14
// baseline (speedup 1.0000x reference)
#include <cuda_runtime.h>
#include <cuda_fp16.h>
#include <math.h>
#include <stdint.h>

#define Bz   256
#define Pz   196
#define Hz   1024
#define Az   512
#define MBIG (Bz * Pz)   // 50176 = 392 * 128

// ------------------------------------------------------------------
// device scratch (allocations forbidden)
// ------------------------------------------------------------------
__device__ float  g_sent_aff[Bz * Hz];
__device__ float  g_hid_aff [Bz * Hz];
__device__ float  g_sent_att[Bz * Az];
__device__ float  g_hid_att [Bz * Az];
__device__ float  g_alpha_part[4 * MBIG];
__device__ float  g_ctx     [Bz * Hz];
__device__ float  g_aff_part[2 * 8 * Bz * Hz];  // [hid | sent] split-K=8 slabs
__device__ float  g_att_part[2 * 8 * Bz * Az];
__device__ float  g_fin_part[8 * Bz * Hz];
__device__ __half g_Ah[(size_t)MBIG * Hz];      // spatial fp16 (103 MB)
__device__ __half g_Bh[Hz * Az];                // W_v_att fp16 [K][N]
__device__ int    g_batch_cnt[Bz];              // last-arriver counters

// ------------------------------------------------------------------
__device__ __forceinline__ uint32_t smem_u32(const void* p) {
    uint32_t a;
    asm("{ .reg .u64 t; cvta.to.shared.u64 t, %1; cvt.u32.u64 %0, t; }"
        : "=r"(a) : "l"(p));
    return a;
}
__device__ __forceinline__ void cpa16(uint32_t dst, const void* src) {
    asm volatile("cp.async.cg.shared.global [%0], [%1], 16;"
                 :: "r"(dst), "l"(src) : "memory");
}
#define CP_COMMIT() asm volatile("cp.async.commit_group;" ::: "memory")
#define CP_WAIT(n)  asm volatile("cp.async.wait_group %0;" :: "n"(n) : "memory")

__device__ __forceinline__ void ldsm_x4(uint32_t* r, uint32_t addr) {
    asm volatile("ldmatrix.sync.aligned.m8n8.x4.shared.b16 {%0,%1,%2,%3}, [%4];"
                 : "=r"(r[0]), "=r"(r[1]), "=r"(r[2]), "=r"(r[3]) : "r"(addr));
}
__device__ __forceinline__ void ldsm_x4_t(uint32_t* r, uint32_t addr) {
    asm volatile("ldmatrix.sync.aligned.m8n8.x4.trans.shared.b16 {%0,%1,%2,%3}, [%4];"
                 : "=r"(r[0]), "=r"(r[1]), "=r"(r[2]), "=r"(r[3]) : "r"(addr));
}
__device__ __forceinline__ void mma16816(float* c, const uint32_t* a, const uint32_t* b) {
    asm volatile(
        "mma.sync.aligned.m16n8k16.row.col.f32.f16.f16.f32 "
        "{%0,%1,%2,%3}, {%4,%5,%6,%7}, {%8,%9}, {%0,%1,%2,%3};"
        : "+f"(c[0]), "+f"(c[1]), "+f"(c[2]), "+f"(c[3])
        : "r"(a[0]), "r"(a[1]), "r"(a[2]), "r"(a[3]), "r"(b[0]), "r"(b[1]));
}
__device__ __forceinline__ uint32_t tanh_f16x2(uint32_t x) {
    uint32_t y;
    asm("tanh.approx.f16x2 %0, %1;" : "=r"(y) : "r"(x));
    return y;
}

// ------------------------------------------------------------------
// fp32 -> fp16 conversions (streaming, full MLP)
// ------------------------------------------------------------------
__global__ void convA_kernel(const float* __restrict__ Sp) {
    size_t base = ((size_t)blockIdx.x * 256 + threadIdx.x) * 8;
    float4 x0 = *(const float4*)&Sp[base];
    float4 x1 = *(const float4*)&Sp[base + 4];
    __half2 h[4];
    h[0] = __floats2half2_rn(x0.x, x0.y);
    h[1] = __floats2half2_rn(x0.z, x0.w);
    h[2] = __floats2half2_rn(x1.x, x1.y);
    h[3] = __floats2half2_rn(x1.z, x1.w);
    *(uint4*)&g_Ah[base] = *(uint4*)h;
}
__global__ void convB_kernel(const float* __restrict__ Wv) {
    size_t base = ((size_t)blockIdx.x * 256 + threadIdx.x) * 8;
    float4 x0 = *(const float4*)&Wv[base];
    float4 x1 = *(const float4*)&Wv[base + 4];
    __half2 h[4];
    h[0] = __floats2half2_rn(x0.x, x0.y);
    h[1] = __floats2half2_rn(x0.z, x0.w);
    h[2] = __floats2half2_rn(x1.x, x1.y);
    h[3] = __floats2half2_rn(x1.z, x1.w);
    *(uint4*)&g_Bh[base] = *(uint4*)h;
}

// ------------------------------------------------------------------
// big fused attention GEMM on HMMA, BM=128 BN=128 BK=32
// 3-stage cp.async ring, single launch grid (4 chunks, 392 m-tiles).
// NEW: last-arriver tail — the CTA completing a batch's 4x(covering tiles)
// alpha partials runs that batch's softmax+context inline (drain overlap).
// ------------------------------------------------------------------
#define AS_STRIDE 80
#define BS_STRIDE 272
#define AS_BYTES  10240
#define BS_BYTES  8704
#define STG_BYTES (AS_BYTES + BS_BYTES)
#define NSTAGE    3

__global__ void __launch_bounds__(256, 2)
big_attn_mma(const float* __restrict__ bv,   // (512) b_v_att
             const float* __restrict__ Wa,   // (512) W_alpha
             float* __restrict__ out_w,      // (B,197)
             float* __restrict__ out_beta)   // (B,1)
{
    extern __shared__ char dyn[];
    __shared__ float red[128 * 4];
    __shared__ float sh[256];
    __shared__ float vals[200];
    __shared__ float ws[200];
    __shared__ int   s_do[2];

    const int tid  = threadIdx.x;
    const int wid  = tid >> 5;
    const int lane = tid & 31;
    const int wm   = wid & 1;
    const int wn   = wid >> 1;
    const int m0   = blockIdx.y * 128;
    const int n0g  = blockIdx.x * 128;

    const uint32_t dyn_s = smem_u32(dyn);

    float acc[4][4][4] = {};

    auto prefetch = [&](int kc, int s) {
        const uint32_t as = dyn_s + s * STG_BYTES;
        const uint32_t bs = as + AS_BYTES;
        const int k0 = kc * 32;
#pragma unroll
        for (int g = 0; g < 2; g++) {
            int idx = g * 256 + tid;
            int row = idx >> 2, c = idx & 3;
            cpa16(as + row * AS_STRIDE + c * 16,
                  &g_Ah[(size_t)(m0 + row) * 1024 + k0 + c * 8]);
        }
#pragma unroll
        for (int g = 0; g < 2; g++) {
            int idx = g * 256 + tid;
            int row = idx >> 4, c = idx & 15;
            cpa16(bs + row * BS_STRIDE + c * 16,
                  &g_Bh[(size_t)(k0 + row) * 512 + n0g + c * 8]);
        }
        CP_COMMIT();
    };

    prefetch(0, 0);
    prefetch(1, 1);

    int stage = 0;
    for (int kc = 0; kc < 32; kc++) {
        if (kc < 31) { CP_WAIT(1); } else { CP_WAIT(0); }
        __syncthreads();

        if (kc < 30) {
            int ps = stage + 2; if (ps >= NSTAGE) ps -= NSTAGE;
            prefetch(kc + 2, ps);
        }

        const uint32_t as = dyn_s + stage * STG_BYTES;
        const uint32_t bs = as + AS_BYTES;

#pragma unroll
        for (int k16 = 0; k16 < 2; k16++) {
            uint32_t a_frag[4][4];
            uint32_t b_frag[4][2];
#pragma unroll
            for (int mt = 0; mt < 4; mt++) {
                int row = wm * 64 + mt * 16 + (lane & 15);
                int col = k16 * 16 + ((lane >> 4) << 3);
                ldsm_x4(a_frag[mt], as + row * AS_STRIDE + col * 2);
            }
#pragma unroll
            for (int p = 0; p < 2; p++) {
                int krow = k16 * 16 + ((lane >> 3) & 1) * 8 + (lane & 7);
                int col  = wn * 32 + p * 16 + ((lane >> 4) << 3);
                uint32_t r[4];
                ldsm_x4_t(r, bs + krow * BS_STRIDE + col * 2);
                b_frag[2 * p][0] = r[0]; b_frag[2 * p][1] = r[1];
                b_frag[2 * p + 1][0] = r[2]; b_frag[2 * p + 1][1] = r[3];
            }
#pragma unroll
            for (int mt = 0; mt < 4; mt++)
#pragma unroll
                for (int nt = 0; nt < 4; nt++)
                    mma16816(acc[mt][nt], a_frag[mt], b_frag[nt]);
        }
        stage++; if (stage >= NSTAGE) stage = 0;
    }
    __syncthreads();

    // ---- epilogue: alpha_part[m] = sum_n tanh(D + bv + hid_att) * Wa ----
    const int lane4 = lane & 3, laned4 = lane >> 2;
    float bvv[8], waa[8];
#pragma unroll
    for (int nt = 0; nt < 4; nt++) {
        int ng = n0g + wn * 32 + nt * 8 + lane4 * 2;
        bvv[2 * nt] = bv[ng];     bvv[2 * nt + 1] = bv[ng + 1];
        waa[2 * nt] = Wa[ng];     waa[2 * nt + 1] = Wa[ng + 1];
    }
#pragma unroll
    for (int mt = 0; mt < 4; mt++) {
        float srow[2] = {0.f, 0.f};
#pragma unroll
        for (int h = 0; h < 2; h++) {
            int rloc = wm * 64 + mt * 16 + laned4 + h * 8;
            int bb = (m0 + rloc) / Pz;
            const float* ha = &g_hid_att[(size_t)bb * Az + n0g];
#pragma unroll
            for (int nt = 0; nt < 4; nt++) {
                int cl = wn * 32 + nt * 8 + lane4 * 2;
                float z0 = acc[mt][nt][2 * h]     + bvv[2 * nt]     + ha[cl];
                float z1 = acc[mt][nt][2 * h + 1] + bvv[2 * nt + 1] + ha[cl + 1];
                __half2 zh = __floats2half2_rn(z0, z1);
                uint32_t th = tanh_f16x2(*(uint32_t*)&zh);
                float2 tf = __half22float2(*(__half2*)&th);
                srow[h] += tf.x * waa[2 * nt] + tf.y * waa[2 * nt + 1];
            }
        }
#pragma unroll
        for (int h = 0; h < 2; h++) {
            float s = srow[h];
            s += __shfl_xor_sync(0xffffffffu, s, 1);
            s += __shfl_xor_sync(0xffffffffu, s, 2);
            if (lane4 == 0) {
                int rloc = wm * 64 + mt * 16 + laned4 + h * 8;
                red[rloc * 4 + wn] = s;
            }
        }
    }
    __syncthreads();
    if (tid < 128) {
        float s = red[tid * 4] + red[tid * 4 + 1] + red[tid * 4 + 2] + red[tid * 4 + 3];
        g_alpha_part[(size_t)blockIdx.x * MBIG + m0 + tid] = s;
    }

    // ---- last-arriver bookkeeping (no spin; CUB-style) ----
    __threadfence();   // publish alpha before counting
    if (tid == 0) {
        s_do[0] = -1; s_do[1] = -1;
        int b_lo = m0 / Pz;
        int b_hi = (m0 + 127) / Pz;
        if (b_hi >= Bz) b_hi = Bz - 1;
        int slot = 0;
        for (int b = b_lo; b <= b_hi; b++) {
            int t_lo = (b * Pz) >> 7;
            int t_hi = (b * Pz + Pz - 1) >> 7;
            int target = 4 * (t_hi - t_lo + 1);
            int old = atomicAdd(&g_batch_cnt[b], 1);
            if (old == target - 1) s_do[slot++] = b;
        }
    }
    __syncthreads();

    // ---- fused softmax + context for batches this CTA completed ----
    for (int sel = 0; sel < 2; sel++) {
        int b = s_do[sel];
        if (b < 0) continue;
        __threadfence();   // acquire side (pairs with writers' fences)

        // sentinel logit
        float s = 0.f;
        for (int a = tid; a < Az; a += 256)
            s += tanhf(g_sent_att[b * Az + a] + g_hid_att[b * Az + a]) * Wa[a];
        sh[tid] = s; __syncthreads();
        for (int off = 128; off > 0; off >>= 1) {
            if (tid < off) sh[tid] += sh[tid + off];
            __syncthreads();
        }
        float alpha_sent = sh[0];
        __syncthreads();

        float v = -INFINITY;
        if (tid < 196) {
            int m = b * Pz + tid;
            v = g_alpha_part[m] + g_alpha_part[MBIG + m] +
                g_alpha_part[2 * MBIG + m] + g_alpha_part[3 * MBIG + m];
            vals[tid] = v;
        } else if (tid == 196) {
            v = alpha_sent; vals[196] = v;
        }
        sh[tid] = v; __syncthreads();
        for (int off = 128; off > 0; off >>= 1) {
            if (tid < off) sh[tid] = fmaxf(sh[tid], sh[tid + off]);
            __syncthreads();
        }
        float mx = sh[0]; __syncthreads();

        float e = (tid < 197) ? expf(vals[tid] - mx) : 0.f;
        sh[tid] = e; __syncthreads();
        for (int off = 128; off > 0; off >>= 1) {
            if (tid < off) sh[tid] += sh[tid + off];
            __syncthreads();
        }
        float inv = 1.f / sh[0];
        if (tid < 197) {
            float w = e * inv;
            ws[tid] = w;
            out_w[b * 197 + tid] = w;
            if (tid == 196) out_beta[b] = w;
        }
        __syncthreads();

        // context from fp16 spatial
        const int h0 = tid * 4;
        const __half* hb = &g_Ah[(size_t)b * Pz * 1024 + h0];
        float4 cacc = make_float4(0.f, 0.f, 0.f, 0.f);
#pragma unroll 4
        for (int p = 0; p < Pz; p++) {
            uint2 u = *(const uint2*)(hb + (size_t)p * 1024);
            float2 lo = __half22float2(*(__half2*)&u.x);
            float2 hi = __half22float2(*(__half2*)&u.y);
            float wp = ws[p];
            cacc.x += lo.x * wp; cacc.y += lo.y * wp;
            cacc.z += hi.x * wp; cacc.w += hi.y * wp;
        }
        const int idx = b * 1024 + h0;
        float4 sa = *(const float4*)&g_sent_aff[idx];
        float4 hha = *(const float4*)&g_hid_aff[idx];
        float wl = ws[196];
        cacc.x += sa.x * wl + hha.x; cacc.y += sa.y * wl + hha.y;
        cacc.z += sa.z * wl + hha.z; cacc.w += sa.w * wl + hha.w;
        *(float4*)&g_ctx[idx] = cacc;
        __syncthreads();
    }
}

// ------------------------------------------------------------------
// split-K=8 fp32 GEMM, single job per launch (z = 8 K-splits)
// ------------------------------------------------------------------
__global__ void gemm_splitk(const float* __restrict__ A,
                            const float* __restrict__ W,
                            float* __restrict__ part, int N)
{
    __shared__ __align__(16) float As[16][68];
    __shared__ __align__(16) float Bs[16][68];
    const int ks = blockIdx.z;
    const int tid = threadIdx.x;
    const int tx = tid & 15, ty = tid >> 4;
    const int m0 = blockIdx.y * 64, n0 = blockIdx.x * 64;
    const int kbase = ks * 128;

    const int arow = tid >> 2, acg = (tid & 3) * 4;
    const int brow = tid >> 4, bcol = (tid & 15) * 4;

    float acc[4][4] = {};

    float4 av = *(const float4*)&A[(size_t)(m0 + arow) * 1024 + kbase + acg];
    float4 bw = *(const float4*)&W[(size_t)(kbase + brow) * N + n0 + bcol];

    for (int it = 0; it < 8; it++) {
        As[acg + 0][arow] = av.x; As[acg + 1][arow] = av.y;
        As[acg + 2][arow] = av.z; As[acg + 3][arow] = av.w;
        *(float4*)&Bs[brow][bcol] = bw;
        __syncthreads();

        if (it < 7) {
            int k0 = kbase + (it + 1) * 16;
            av = *(const float4*)&A[(size_t)(m0 + arow) * 1024 + k0 + acg];
            bw = *(const float4*)&W[(size_t)(k0 + brow) * N + n0 + bcol];
        }

#pragma unroll
        for (int k = 0; k < 16; k++) {
            float4 a4 = *(const float4*)&As[k][ty * 4];
            float4 b4 = *(const float4*)&Bs[k][tx * 4];
            float a[4] = {a4.x, a4.y, a4.z, a4.w};
            float b[4] = {b4.x, b4.y, b4.z, b4.w};
#pragma unroll
            for (int i = 0; i < 4; i++)
#pragma unroll
                for (int j = 0; j < 4; j++) acc[i][j] += a[i] * b[j];
        }
        __syncthreads();
    }

    float* out = part + (size_t)ks * 256 * N;
#pragma unroll
    for (int i = 0; i < 4; i++) {
        int m = m0 + ty * 4 + i;
#pragma unroll
        for (int j = 0; j < 4; j++)
            out[(size_t)m * N + n0 + tx * 4 + j] = acc[i][j];
    }
}

// combine 8 split-K partials + bias + activation (0=none,1=relu,2=tanh)
__global__ void combine1(const float* __restrict__ part,
                         const float* __restrict__ bias,
                         float* __restrict__ o, int N, int act)
{
    const size_t e = ((size_t)blockIdx.x * 256 + threadIdx.x) * 4;
    const size_t slab = (size_t)256 * N;
    float4 s = *(const float4*)(part + e);
#pragma unroll
    for (int t = 1; t < 8; t++) {
        float4 q = *(const float4*)(part + t * slab + e);
        s.x += q.x; s.y += q.y; s.z += q.z; s.w += q.w;
    }
    const int n = (int)(e & (size_t)(N - 1));
    float4 bvec = *(const float4*)&bias[n];
    s.x += bvec.x; s.y += bvec.y; s.z += bvec.z; s.w += bvec.w;
    if (act == 1) {
        s.x = fmaxf(s.x, 0.f); s.y = fmaxf(s.y, 0.f);
        s.z = fmaxf(s.z, 0.f); s.w = fmaxf(s.w, 0.f);
    } else if (act == 2) {
        s.x = tanhf(s.x); s.y = tanhf(s.y); s.z = tanhf(s.z); s.w = tanhf(s.w);
    }
    *(float4*)(o + e) = s;
}

// ------------------------------------------------------------------
extern "C" void kernel_launch(void* const* d_in, const int* in_sizes, int n_in,
                              void* d_out, int out_size)
{
    (void)in_sizes; (void)n_in; (void)out_size;
    const float* spatial   = (const float*)d_in[0];
    const float* decoder   = (const float*)d_in[1];
    const float* st        = (const float*)d_in[2];
    const float* W_sen_aff = (const float*)d_in[3];
    const float* b_sen_aff = (const float*)d_in[4];
    const float* W_sen_att = (const float*)d_in[5];
    const float* b_sen_att = (const float*)d_in[6];
    const float* W_h_aff   = (const float*)d_in[7];
    const float* b_h_aff   = (const float*)d_in[8];
    const float* W_h_att   = (const float*)d_in[9];
    const float* b_h_att   = (const float*)d_in[10];
    const float* W_v_att   = (const float*)d_in[11];
    const float* b_v_att   = (const float*)d_in[12];
    const float* W_alpha   = (const float*)d_in[13];
    // d_in[14] = b_alpha: softmax-invariant constant, dropped
    const float* W_ctx     = (const float*)d_in[15];
    const float* b_ctx     = (const float*)d_in[16];

    float* out      = (float*)d_out;
    float* out_l    = out;
    float* out_w    = out + Bz * Hz;
    float* out_beta = out + Bz * Hz + Bz * 197;

    float *sa, *ha, *st_att, *h_att, *ctx, *affp, *attp, *finp;
    int* bcnt;
    cudaGetSymbolAddress((void**)&sa,     g_sent_aff);
    cudaGetSymbolAddress((void**)&ha,     g_hid_aff);
    cudaGetSymbolAddress((void**)&st_att, g_sent_att);
    cudaGetSymbolAddress((void**)&h_att,  g_hid_att);
    cudaGetSymbolAddress((void**)&ctx,    g_ctx);
    cudaGetSymbolAddress((void**)&affp,   g_aff_part);
    cudaGetSymbolAddress((void**)&attp,   g_att_part);
    cudaGetSymbolAddress((void**)&finp,   g_fin_part);
    cudaGetSymbolAddress((void**)&bcnt,   g_batch_cnt);

    const size_t aff_slabs = (size_t)8 * 256 * Hz;
    const size_t att_slabs = (size_t)8 * 256 * Az;
    float* affp_hid  = affp;
    float* affp_sent = affp + aff_slabs;
    float* attp_hid  = attp;
    float* attp_sent = attp + att_slabs;

    const int BIG_SMEM = NSTAGE * STG_BYTES;   // 56832
    cudaFuncSetAttribute(big_attn_mma,
                         cudaFuncAttributeMaxDynamicSharedMemorySize, BIG_SMEM);

    static cudaStream_t s2 = nullptr, s3 = nullptr;
    static cudaEvent_t ev_fork = nullptr, ev_conv = nullptr, ev_sent = nullptr;
    if (!s2) {
        cudaStreamCreateWithFlags(&s2, cudaStreamNonBlocking);
        cudaStreamCreateWithFlags(&s3, cudaStreamNonBlocking);
        cudaEventCreateWithFlags(&ev_fork, cudaEventDisableTiming);
        cudaEventCreateWithFlags(&ev_conv, cudaEventDisableTiming);
        cudaEventCreateWithFlags(&ev_sent, cudaEventDisableTiming);
    }

    // reset last-arriver counters (graph-capturable, not an allocation)
    cudaMemsetAsync(bcnt, 0, Bz * sizeof(int), 0);

    // ---- fork ----
    cudaEventRecord(ev_fork, 0);
    cudaStreamWaitEvent(s2, ev_fork, 0);
    cudaStreamWaitEvent(s3, ev_fork, 0);

    // s2: conversions (run concurrently with the hidden chain on main)
    convB_kernel<<<256, 256, 0, s2>>>(W_v_att);
    convA_kernel<<<25088, 256, 0, s2>>>(spatial);
    cudaEventRecord(ev_conv, s2);

    // s3: sentinel chain (consumed by the fused softmax tail)
    gemm_splitk<<<dim3(16, 4, 8), 256, 0, s3>>>(st, W_sen_aff, affp_sent, Hz);
    combine1<<<256, 256, 0, s3>>>(affp_sent, b_sen_aff, sa, Hz, 1);
    gemm_splitk<<<dim3(8, 4, 8), 256, 0, s3>>>(sa, W_sen_att, attp_sent, Az);
    combine1<<<128, 256, 0, s3>>>(attp_sent, b_sen_att, st_att, Az, 0);
    cudaEventRecord(ev_sent, s3);

    // main: hidden chain (gates the big GEMM)
    gemm_splitk<<<dim3(16, 4, 8), 256>>>(decoder, W_h_aff, affp_hid, Hz);
    combine1<<<256, 256>>>(affp_hid, b_h_aff, ha, Hz, 2);
    gemm_splitk<<<dim3(8, 4, 8), 256>>>(ha, W_h_att, attp_hid, Az);
    combine1<<<128, 256>>>(attp_hid, b_h_att, h_att, Az, 0);

    // big GEMM + fused softmax/context tail (needs conv + sentinel chain)
    cudaStreamWaitEvent(0, ev_conv, 0);
    cudaStreamWaitEvent(0, ev_sent, 0);
    big_attn_mma<<<dim3(4, 392), 256, BIG_SMEM>>>(b_v_att, W_alpha,
                                                  out_w, out_beta);

    // out_l = tanh(ctx @ W_ctx + b_ctx)
    gemm_splitk<<<dim3(16, 4, 8), 256>>>(ctx, W_ctx, finp, Hz);
    combine1<<<256, 256>>>(finp, b_ctx, out_l, Hz, 2);
}

// round 15
// speedup vs baseline: 1.0528x; 1.0528x over previous
#include <cuda_runtime.h>
#include <cuda_fp16.h>
#include <math.h>
#include <stdint.h>

#define Bz   256
#define Pz   196
#define Hz   1024
#define Az   512
#define MBIG (Bz * Pz)   // 50176 = 392 * 128

// ------------------------------------------------------------------
// device scratch (allocations forbidden)
// ------------------------------------------------------------------
__device__ float  g_sent_aff[Bz * Hz];
__device__ float  g_hid_aff [Bz * Hz];
__device__ float  g_sent_att[Bz * Az];
__device__ float  g_hid_att [Bz * Az];
__device__ float  g_alpha_part[4 * MBIG];
__device__ float  g_ctx     [Bz * Hz];
__device__ float  g_aff_part[2 * 8 * Bz * Hz];  // [hid | sent] split-K=8 slabs
__device__ float  g_att_part[2 * 8 * Bz * Az];
__device__ float  g_fin_part[8 * Bz * Hz];
__device__ __half g_Ah[(size_t)MBIG * Hz];      // spatial fp16 (103 MB)
__device__ __half g_Bh[Hz * Az];                // W_v_att fp16 [K][N]

// ------------------------------------------------------------------
__device__ __forceinline__ uint32_t smem_u32(const void* p) {
    uint32_t a;
    asm("{ .reg .u64 t; cvta.to.shared.u64 t, %1; cvt.u32.u64 %0, t; }"
        : "=r"(a) : "l"(p));
    return a;
}
__device__ __forceinline__ void cpa16(uint32_t dst, const void* src) {
    asm volatile("cp.async.cg.shared.global [%0], [%1], 16;"
                 :: "r"(dst), "l"(src) : "memory");
}
#define CP_COMMIT() asm volatile("cp.async.commit_group;" ::: "memory")
#define CP_WAIT(n)  asm volatile("cp.async.wait_group %0;" :: "n"(n) : "memory")

__device__ __forceinline__ void ldsm_x4(uint32_t* r, uint32_t addr) {
    asm volatile("ldmatrix.sync.aligned.m8n8.x4.shared.b16 {%0,%1,%2,%3}, [%4];"
                 : "=r"(r[0]), "=r"(r[1]), "=r"(r[2]), "=r"(r[3]) : "r"(addr));
}
__device__ __forceinline__ void ldsm_x4_t(uint32_t* r, uint32_t addr) {
    asm volatile("ldmatrix.sync.aligned.m8n8.x4.trans.shared.b16 {%0,%1,%2,%3}, [%4];"
                 : "=r"(r[0]), "=r"(r[1]), "=r"(r[2]), "=r"(r[3]) : "r"(addr));
}
__device__ __forceinline__ void mma16816(float* c, const uint32_t* a, const uint32_t* b) {
    asm volatile(
        "mma.sync.aligned.m16n8k16.row.col.f32.f16.f16.f32 "
        "{%0,%1,%2,%3}, {%4,%5,%6,%7}, {%8,%9}, {%0,%1,%2,%3};"
        : "+f"(c[0]), "+f"(c[1]), "+f"(c[2]), "+f"(c[3])
        : "r"(a[0]), "r"(a[1]), "r"(a[2]), "r"(a[3]), "r"(b[0]), "r"(b[1]));
}
__device__ __forceinline__ uint32_t tanh_f16x2(uint32_t x) {
    uint32_t y;
    asm("tanh.approx.f16x2 %0, %1;" : "=r"(y) : "r"(x));
    return y;
}

// ------------------------------------------------------------------
// fp32 -> fp16 conversions (streaming, full MLP)
// ------------------------------------------------------------------
__global__ void convA_kernel(const float* __restrict__ Sp) {
    size_t base = ((size_t)blockIdx.x * 256 + threadIdx.x) * 8;
    float4 x0 = *(const float4*)&Sp[base];
    float4 x1 = *(const float4*)&Sp[base + 4];
    __half2 h[4];
    h[0] = __floats2half2_rn(x0.x, x0.y);
    h[1] = __floats2half2_rn(x0.z, x0.w);
    h[2] = __floats2half2_rn(x1.x, x1.y);
    h[3] = __floats2half2_rn(x1.z, x1.w);
    *(uint4*)&g_Ah[base] = *(uint4*)h;
}
__global__ void convB_kernel(const float* __restrict__ Wv) {
    size_t base = ((size_t)blockIdx.x * 256 + threadIdx.x) * 8;
    float4 x0 = *(const float4*)&Wv[base];
    float4 x1 = *(const float4*)&Wv[base + 4];
    __half2 h[4];
    h[0] = __floats2half2_rn(x0.x, x0.y);
    h[1] = __floats2half2_rn(x0.z, x0.w);
    h[2] = __floats2half2_rn(x1.x, x1.y);
    h[3] = __floats2half2_rn(x1.z, x1.w);
    *(uint4*)&g_Bh[base] = *(uint4*)h;
}

// ------------------------------------------------------------------
// big fused attention GEMM on HMMA, BM=128 BN=128 BK=32
// 3-stage cp.async ring, single launch grid (4 chunks, 392 m-tiles).
// (R14's in-kernel softmax tail regressed +20us — keep the tail OUT.)
// ------------------------------------------------------------------
#define AS_STRIDE 80
#define BS_STRIDE 272
#define AS_BYTES  10240
#define BS_BYTES  8704
#define STG_BYTES (AS_BYTES + BS_BYTES)
#define NSTAGE    3

__global__ void __launch_bounds__(256, 2)
big_attn_mma(const float* __restrict__ bv,   // (512)
             const float* __restrict__ Wa)   // (512)
{
    extern __shared__ char dyn[];
    __shared__ float red[128 * 4];

    const int tid  = threadIdx.x;
    const int wid  = tid >> 5;
    const int lane = tid & 31;
    const int wm   = wid & 1;
    const int wn   = wid >> 1;
    const int m0   = blockIdx.y * 128;
    const int n0g  = blockIdx.x * 128;

    const uint32_t dyn_s = smem_u32(dyn);

    float acc[4][4][4] = {};

    auto prefetch = [&](int kc, int s) {
        const uint32_t as = dyn_s + s * STG_BYTES;
        const uint32_t bs = as + AS_BYTES;
        const int k0 = kc * 32;
#pragma unroll
        for (int g = 0; g < 2; g++) {
            int idx = g * 256 + tid;
            int row = idx >> 2, c = idx & 3;
            cpa16(as + row * AS_STRIDE + c * 16,
                  &g_Ah[(size_t)(m0 + row) * 1024 + k0 + c * 8]);
        }
#pragma unroll
        for (int g = 0; g < 2; g++) {
            int idx = g * 256 + tid;
            int row = idx >> 4, c = idx & 15;
            cpa16(bs + row * BS_STRIDE + c * 16,
                  &g_Bh[(size_t)(k0 + row) * 512 + n0g + c * 8]);
        }
        CP_COMMIT();
    };

    prefetch(0, 0);
    prefetch(1, 1);

    int stage = 0;
    for (int kc = 0; kc < 32; kc++) {
        if (kc < 31) { CP_WAIT(1); } else { CP_WAIT(0); }
        __syncthreads();

        if (kc < 30) {
            int ps = stage + 2; if (ps >= NSTAGE) ps -= NSTAGE;
            prefetch(kc + 2, ps);
        }

        const uint32_t as = dyn_s + stage * STG_BYTES;
        const uint32_t bs = as + AS_BYTES;

#pragma unroll
        for (int k16 = 0; k16 < 2; k16++) {
            uint32_t a_frag[4][4];
            uint32_t b_frag[4][2];
#pragma unroll
            for (int mt = 0; mt < 4; mt++) {
                int row = wm * 64 + mt * 16 + (lane & 15);
                int col = k16 * 16 + ((lane >> 4) << 3);
                ldsm_x4(a_frag[mt], as + row * AS_STRIDE + col * 2);
            }
#pragma unroll
            for (int p = 0; p < 2; p++) {
                int krow = k16 * 16 + ((lane >> 3) & 1) * 8 + (lane & 7);
                int col  = wn * 32 + p * 16 + ((lane >> 4) << 3);
                uint32_t r[4];
                ldsm_x4_t(r, bs + krow * BS_STRIDE + col * 2);
                b_frag[2 * p][0] = r[0]; b_frag[2 * p][1] = r[1];
                b_frag[2 * p + 1][0] = r[2]; b_frag[2 * p + 1][1] = r[3];
            }
#pragma unroll
            for (int mt = 0; mt < 4; mt++)
#pragma unroll
                for (int nt = 0; nt < 4; nt++)
                    mma16816(acc[mt][nt], a_frag[mt], b_frag[nt]);
        }
        stage++; if (stage >= NSTAGE) stage = 0;
    }
    __syncthreads();

    // ---- epilogue: alpha_part[m] = sum_n tanh(D + bv + hid_att) * Wa ----
    const int lane4 = lane & 3, laned4 = lane >> 2;
    float bvv[8], waa[8];
#pragma unroll
    for (int nt = 0; nt < 4; nt++) {
        int ng = n0g + wn * 32 + nt * 8 + lane4 * 2;
        bvv[2 * nt] = bv[ng];     bvv[2 * nt + 1] = bv[ng + 1];
        waa[2 * nt] = Wa[ng];     waa[2 * nt + 1] = Wa[ng + 1];
    }
#pragma unroll
    for (int mt = 0; mt < 4; mt++) {
        float srow[2] = {0.f, 0.f};
#pragma unroll
        for (int h = 0; h < 2; h++) {
            int rloc = wm * 64 + mt * 16 + laned4 + h * 8;
            int bb = (m0 + rloc) / Pz;
            const float* ha = &g_hid_att[(size_t)bb * Az + n0g];
#pragma unroll
            for (int nt = 0; nt < 4; nt++) {
                int cl = wn * 32 + nt * 8 + lane4 * 2;
                float z0 = acc[mt][nt][2 * h]     + bvv[2 * nt]     + ha[cl];
                float z1 = acc[mt][nt][2 * h + 1] + bvv[2 * nt + 1] + ha[cl + 1];
                __half2 zh = __floats2half2_rn(z0, z1);
                uint32_t th = tanh_f16x2(*(uint32_t*)&zh);
                float2 tf = __half22float2(*(__half2*)&th);
                srow[h] += tf.x * waa[2 * nt] + tf.y * waa[2 * nt + 1];
            }
        }
#pragma unroll
        for (int h = 0; h < 2; h++) {
            float s = srow[h];
            s += __shfl_xor_sync(0xffffffffu, s, 1);
            s += __shfl_xor_sync(0xffffffffu, s, 2);
            if (lane4 == 0) {
                int rloc = wm * 64 + mt * 16 + laned4 + h * 8;
                red[rloc * 4 + wn] = s;
            }
        }
    }
    __syncthreads();
    if (tid < 128) {
        float s = red[tid * 4] + red[tid * 4 + 1] + red[tid * 4 + 2] + red[tid * 4 + 3];
        g_alpha_part[(size_t)blockIdx.x * MBIG + m0 + tid] = s;
    }
}

// ------------------------------------------------------------------
// split-K=8 fp32 GEMM, single job per launch (z = 8 K-splits)
// ------------------------------------------------------------------
__global__ void gemm_splitk(const float* __restrict__ A,
                            const float* __restrict__ W,
                            float* __restrict__ part, int N)
{
    __shared__ __align__(16) float As[16][68];
    __shared__ __align__(16) float Bs[16][68];
    const int ks = blockIdx.z;
    const int tid = threadIdx.x;
    const int tx = tid & 15, ty = tid >> 4;
    const int m0 = blockIdx.y * 64, n0 = blockIdx.x * 64;
    const int kbase = ks * 128;

    const int arow = tid >> 2, acg = (tid & 3) * 4;
    const int brow = tid >> 4, bcol = (tid & 15) * 4;

    float acc[4][4] = {};

    float4 av = *(const float4*)&A[(size_t)(m0 + arow) * 1024 + kbase + acg];
    float4 bw = *(const float4*)&W[(size_t)(kbase + brow) * N + n0 + bcol];

    for (int it = 0; it < 8; it++) {
        As[acg + 0][arow] = av.x; As[acg + 1][arow] = av.y;
        As[acg + 2][arow] = av.z; As[acg + 3][arow] = av.w;
        *(float4*)&Bs[brow][bcol] = bw;
        __syncthreads();

        if (it < 7) {
            int k0 = kbase + (it + 1) * 16;
            av = *(const float4*)&A[(size_t)(m0 + arow) * 1024 + k0 + acg];
            bw = *(const float4*)&W[(size_t)(k0 + brow) * N + n0 + bcol];
        }

#pragma unroll
        for (int k = 0; k < 16; k++) {
            float4 a4 = *(const float4*)&As[k][ty * 4];
            float4 b4 = *(const float4*)&Bs[k][tx * 4];
            float a[4] = {a4.x, a4.y, a4.z, a4.w};
            float b[4] = {b4.x, b4.y, b4.z, b4.w};
#pragma unroll
            for (int i = 0; i < 4; i++)
#pragma unroll
                for (int j = 0; j < 4; j++) acc[i][j] += a[i] * b[j];
        }
        __syncthreads();
    }

    float* out = part + (size_t)ks * 256 * N;
#pragma unroll
    for (int i = 0; i < 4; i++) {
        int m = m0 + ty * 4 + i;
#pragma unroll
        for (int j = 0; j < 4; j++)
            out[(size_t)m * N + n0 + tx * 4 + j] = acc[i][j];
    }
}

// combine 8 split-K partials + bias + activation (0=none,1=relu,2=tanh)
__global__ void combine1(const float* __restrict__ part,
                         const float* __restrict__ bias,
                         float* __restrict__ o, int N, int act)
{
    const size_t e = ((size_t)blockIdx.x * 256 + threadIdx.x) * 4;
    const size_t slab = (size_t)256 * N;
    float4 s = *(const float4*)(part + e);
#pragma unroll
    for (int t = 1; t < 8; t++) {
        float4 q = *(const float4*)(part + t * slab + e);
        s.x += q.x; s.y += q.y; s.z += q.z; s.w += q.w;
    }
    const int n = (int)(e & (size_t)(N - 1));
    float4 bvec = *(const float4*)&bias[n];
    s.x += bvec.x; s.y += bvec.y; s.z += bvec.z; s.w += bvec.w;
    if (act == 1) {
        s.x = fmaxf(s.x, 0.f); s.y = fmaxf(s.y, 0.f);
        s.z = fmaxf(s.z, 0.f); s.w = fmaxf(s.w, 0.f);
    } else if (act == 2) {
        s.x = tanhf(s.x); s.y = tanhf(s.y); s.z = tanhf(s.z); s.w = tanhf(s.w);
    }
    *(float4*)(o + e) = s;
}

// ------------------------------------------------------------------
// softmax over 197 logits per batch (sentinel computed here)
// ------------------------------------------------------------------
__global__ void softmax_kernel(const float* __restrict__ Wa,
                               float* __restrict__ out_w,
                               float* __restrict__ out_beta)
{
    const int b = blockIdx.x;
    const int tid = threadIdx.x;
    __shared__ float sh[256];
    __shared__ float vals[197];

    float s = 0.f;
    for (int a = tid; a < 512; a += 256)
        s += tanhf(g_sent_att[b * 512 + a] + g_hid_att[b * 512 + a]) * Wa[a];
    sh[tid] = s; __syncthreads();
    for (int off = 128; off > 0; off >>= 1) {
        if (tid < off) sh[tid] += sh[tid + off];
        __syncthreads();
    }
    float alpha_sent = sh[0];
    __syncthreads();

    float v = -INFINITY;
    if (tid < 196) {
        int m = b * 196 + tid;
        v = g_alpha_part[m] + g_alpha_part[MBIG + m] +
            g_alpha_part[2 * MBIG + m] + g_alpha_part[3 * MBIG + m];
        vals[tid] = v;
    } else if (tid == 196) {
        v = alpha_sent; vals[196] = v;
    }
    sh[tid] = v; __syncthreads();
    for (int off = 128; off > 0; off >>= 1) {
        if (tid < off) sh[tid] = fmaxf(sh[tid], sh[tid + off]);
        __syncthreads();
    }
    float mx = sh[0]; __syncthreads();

    float e = (tid < 197) ? expf(vals[tid] - mx) : 0.f;
    sh[tid] = e; __syncthreads();
    for (int off = 128; off > 0; off >>= 1) {
        if (tid < off) sh[tid] += sh[tid + off];
        __syncthreads();
    }
    float inv = 1.f / sh[0];
    if (tid < 197) {
        float w = e * inv;
        out_w[b * 197 + tid] = w;
        if (tid == 196) out_beta[b] = w;
    }
}

// ------------------------------------------------------------------
// context: grid (B, 2), each CTA covers 512 H-halves -> 512 CTAs
// (3.46 waves vs the merged kernel's 1.73 — better balance + MLP)
// ------------------------------------------------------------------
__global__ void context_kernel(const float* __restrict__ w)
{
    const int b = blockIdx.x;
    const int half0 = blockIdx.y * 512;     // 0 or 512
    const int tid = threadIdx.x;            // 128 threads x 4 halves = 512
    __shared__ float ws[197];
    for (int i = tid; i < 197; i += 128) ws[i] = w[b * 197 + i];
    __syncthreads();

    const int h0 = half0 + tid * 4;
    const __half* hb = &g_Ah[(size_t)b * Pz * 1024 + h0];
    float4 acc = make_float4(0.f, 0.f, 0.f, 0.f);
#pragma unroll 4
    for (int p = 0; p < Pz; p++) {
        uint2 u = *(const uint2*)(hb + (size_t)p * 1024);
        float2 lo = __half22float2(*(__half2*)&u.x);
        float2 hi = __half22float2(*(__half2*)&u.y);
        float wp = ws[p];
        acc.x += lo.x * wp; acc.y += lo.y * wp;
        acc.z += hi.x * wp; acc.w += hi.y * wp;
    }
    const int idx = b * 1024 + h0;
    float4 sa = *(const float4*)&g_sent_aff[idx];
    float4 ha = *(const float4*)&g_hid_aff[idx];
    float wl = ws[196];
    acc.x += sa.x * wl + ha.x; acc.y += sa.y * wl + ha.y;
    acc.z += sa.z * wl + ha.z; acc.w += sa.w * wl + ha.w;
    *(float4*)&g_ctx[idx] = acc;
}

// ------------------------------------------------------------------
extern "C" void kernel_launch(void* const* d_in, const int* in_sizes, int n_in,
                              void* d_out, int out_size)
{
    (void)in_sizes; (void)n_in; (void)out_size;
    const float* spatial   = (const float*)d_in[0];
    const float* decoder   = (const float*)d_in[1];
    const float* st        = (const float*)d_in[2];
    const float* W_sen_aff = (const float*)d_in[3];
    const float* b_sen_aff = (const float*)d_in[4];
    const float* W_sen_att = (const float*)d_in[5];
    const float* b_sen_att = (const float*)d_in[6];
    const float* W_h_aff   = (const float*)d_in[7];
    const float* b_h_aff   = (const float*)d_in[8];
    const float* W_h_att   = (const float*)d_in[9];
    const float* b_h_att   = (const float*)d_in[10];
    const float* W_v_att   = (const float*)d_in[11];
    const float* b_v_att   = (const float*)d_in[12];
    const float* W_alpha   = (const float*)d_in[13];
    // d_in[14] = b_alpha: softmax-invariant constant, dropped
    const float* W_ctx     = (const float*)d_in[15];
    const float* b_ctx     = (const float*)d_in[16];

    float* out      = (float*)d_out;
    float* out_l    = out;
    float* out_w    = out + Bz * Hz;
    float* out_beta = out + Bz * Hz + Bz * 197;

    float *sa, *ha, *st_att, *h_att, *ctx, *affp, *attp, *finp;
    cudaGetSymbolAddress((void**)&sa,     g_sent_aff);
    cudaGetSymbolAddress((void**)&ha,     g_hid_aff);
    cudaGetSymbolAddress((void**)&st_att, g_sent_att);
    cudaGetSymbolAddress((void**)&h_att,  g_hid_att);
    cudaGetSymbolAddress((void**)&ctx,    g_ctx);
    cudaGetSymbolAddress((void**)&affp,   g_aff_part);
    cudaGetSymbolAddress((void**)&attp,   g_att_part);
    cudaGetSymbolAddress((void**)&finp,   g_fin_part);

    const size_t aff_slabs = (size_t)8 * 256 * Hz;
    const size_t att_slabs = (size_t)8 * 256 * Az;
    float* affp_hid  = affp;
    float* affp_sent = affp + aff_slabs;
    float* attp_hid  = attp;
    float* attp_sent = attp + att_slabs;

    const int BIG_SMEM = NSTAGE * STG_BYTES;   // 56832
    cudaFuncSetAttribute(big_attn_mma,
                         cudaFuncAttributeMaxDynamicSharedMemorySize, BIG_SMEM);

    static cudaStream_t s2 = nullptr, s3 = nullptr;
    static cudaEvent_t ev_fork = nullptr, ev_conv = nullptr, ev_sent = nullptr;
    if (!s2) {
        cudaStreamCreateWithFlags(&s2, cudaStreamNonBlocking);
        cudaStreamCreateWithFlags(&s3, cudaStreamNonBlocking);
        cudaEventCreateWithFlags(&ev_fork, cudaEventDisableTiming);
        cudaEventCreateWithFlags(&ev_conv, cudaEventDisableTiming);
        cudaEventCreateWithFlags(&ev_sent, cudaEventDisableTiming);
    }

    // ---- fork ----
    cudaEventRecord(ev_fork, 0);
    cudaStreamWaitEvent(s2, ev_fork, 0);
    cudaStreamWaitEvent(s3, ev_fork, 0);

    // s2: conversions (run concurrently with the hidden chain on main)
    convB_kernel<<<256, 256, 0, s2>>>(W_v_att);
    convA_kernel<<<25088, 256, 0, s2>>>(spatial);
    cudaEventRecord(ev_conv, s2);

    // s3: sentinel chain (needed only by softmax)
    gemm_splitk<<<dim3(16, 4, 8), 256, 0, s3>>>(st, W_sen_aff, affp_sent, Hz);
    combine1<<<256, 256, 0, s3>>>(affp_sent, b_sen_aff, sa, Hz, 1);
    gemm_splitk<<<dim3(8, 4, 8), 256, 0, s3>>>(sa, W_sen_att, attp_sent, Az);
    combine1<<<128, 256, 0, s3>>>(attp_sent, b_sen_att, st_att, Az, 0);
    cudaEventRecord(ev_sent, s3);

    // main: hidden chain (gates the big GEMM)
    gemm_splitk<<<dim3(16, 4, 8), 256>>>(decoder, W_h_aff, affp_hid, Hz);
    combine1<<<256, 256>>>(affp_hid, b_h_aff, ha, Hz, 2);
    gemm_splitk<<<dim3(8, 4, 8), 256>>>(ha, W_h_att, attp_hid, Az);
    combine1<<<128, 256>>>(attp_hid, b_h_att, h_att, Az, 0);

    // big GEMM: single launch (one ramp + one drain)
    cudaStreamWaitEvent(0, ev_conv, 0);
    big_attn_mma<<<dim3(4, 392), 256, BIG_SMEM>>>(b_v_att, W_alpha);

    // softmax (tiny) then context (512 CTAs, balanced waves)
    cudaStreamWaitEvent(0, ev_sent, 0);
    softmax_kernel<<<Bz, 256>>>(W_alpha, out_w, out_beta);
    context_kernel<<<dim3(Bz, 2), 128>>>(out_w);

    // out_l = tanh(ctx @ W_ctx + b_ctx)
    gemm_splitk<<<dim3(16, 4, 8), 256>>>(ctx, W_ctx, finp, Hz);
    combine1<<<256, 256>>>(finp, b_ctx, out_l, Hz, 2);
}

// round 16
// speedup vs baseline: 1.0588x; 1.0057x over previous
#include <cuda_runtime.h>
#include <cuda_fp16.h>
#include <math.h>
#include <stdint.h>

#define Bz   256
#define Pz   196
#define Hz   1024
#define Az   512
#define MBIG (Bz * Pz)   // 50176 = 392 * 128

// ------------------------------------------------------------------
// device scratch (allocations forbidden)
// ------------------------------------------------------------------
__device__ float  g_sent_aff[Bz * Hz];
__device__ float  g_hid_aff [Bz * Hz];
__device__ float  g_sent_att[Bz * Az];
__device__ float  g_hid_att [Bz * Az];
__device__ float  g_alpha_part[4 * MBIG];
__device__ float  g_ctx     [Bz * Hz];
__device__ float  g_aff_part[2 * 8 * Bz * Hz];  // [hid | sent] split-K=8 slabs
__device__ float  g_att_part[2 * 8 * Bz * Az];
__device__ float  g_fin_part[8 * Bz * Hz];
__device__ __half g_Ah[(size_t)MBIG * Hz];      // spatial fp16 (103 MB)
__device__ __half g_Bh[Hz * Az];                // W_v_att fp16 [K][N]

// ------------------------------------------------------------------
__device__ __forceinline__ uint32_t smem_u32(const void* p) {
    uint32_t a;
    asm("{ .reg .u64 t; cvta.to.shared.u64 t, %1; cvt.u32.u64 %0, t; }"
        : "=r"(a) : "l"(p));
    return a;
}
__device__ __forceinline__ void cpa16(uint32_t dst, const void* src) {
    asm volatile("cp.async.cg.shared.global [%0], [%1], 16;"
                 :: "r"(dst), "l"(src) : "memory");
}
#define CP_COMMIT() asm volatile("cp.async.commit_group;" ::: "memory")
#define CP_WAIT(n)  asm volatile("cp.async.wait_group %0;" :: "n"(n) : "memory")

__device__ __forceinline__ void ldsm_x4(uint32_t* r, uint32_t addr) {
    asm volatile("ldmatrix.sync.aligned.m8n8.x4.shared.b16 {%0,%1,%2,%3}, [%4];"
                 : "=r"(r[0]), "=r"(r[1]), "=r"(r[2]), "=r"(r[3]) : "r"(addr));
}
__device__ __forceinline__ void ldsm_x4_t(uint32_t* r, uint32_t addr) {
    asm volatile("ldmatrix.sync.aligned.m8n8.x4.trans.shared.b16 {%0,%1,%2,%3}, [%4];"
                 : "=r"(r[0]), "=r"(r[1]), "=r"(r[2]), "=r"(r[3]) : "r"(addr));
}
__device__ __forceinline__ void mma16816(float* c, const uint32_t* a, const uint32_t* b) {
    asm volatile(
        "mma.sync.aligned.m16n8k16.row.col.f32.f16.f16.f32 "
        "{%0,%1,%2,%3}, {%4,%5,%6,%7}, {%8,%9}, {%0,%1,%2,%3};"
        : "+f"(c[0]), "+f"(c[1]), "+f"(c[2]), "+f"(c[3])
        : "r"(a[0]), "r"(a[1]), "r"(a[2]), "r"(a[3]), "r"(b[0]), "r"(b[1]));
}
__device__ __forceinline__ uint32_t tanh_f16x2(uint32_t x) {
    uint32_t y;
    asm("tanh.approx.f16x2 %0, %1;" : "=r"(y) : "r"(x));
    return y;
}

// ------------------------------------------------------------------
// fp32 -> fp16 conversions (streaming, full MLP)
// ------------------------------------------------------------------
__global__ void convA_kernel(const float* __restrict__ Sp) {
    size_t base = ((size_t)blockIdx.x * 256 + threadIdx.x) * 8;
    float4 x0 = *(const float4*)&Sp[base];
    float4 x1 = *(const float4*)&Sp[base + 4];
    __half2 h[4];
    h[0] = __floats2half2_rn(x0.x, x0.y);
    h[1] = __floats2half2_rn(x0.z, x0.w);
    h[2] = __floats2half2_rn(x1.x, x1.y);
    h[3] = __floats2half2_rn(x1.z, x1.w);
    *(uint4*)&g_Ah[base] = *(uint4*)h;
}
__global__ void convB_kernel(const float* __restrict__ Wv) {
    size_t base = ((size_t)blockIdx.x * 256 + threadIdx.x) * 8;
    float4 x0 = *(const float4*)&Wv[base];
    float4 x1 = *(const float4*)&Wv[base + 4];
    __half2 h[4];
    h[0] = __floats2half2_rn(x0.x, x0.y);
    h[1] = __floats2half2_rn(x0.z, x0.w);
    h[2] = __floats2half2_rn(x1.x, x1.y);
    h[3] = __floats2half2_rn(x1.z, x1.w);
    *(uint4*)&g_Bh[base] = *(uint4*)h;
}

// ------------------------------------------------------------------
// big fused attention GEMM on HMMA, BM=128 BN=128 BK=32
// 3-stage cp.async ring, single launch grid (4 chunks, 392 m-tiles).
// ------------------------------------------------------------------
#define AS_STRIDE 80
#define BS_STRIDE 272
#define AS_BYTES  10240
#define BS_BYTES  8704
#define STG_BYTES (AS_BYTES + BS_BYTES)
#define NSTAGE    3

__global__ void __launch_bounds__(256, 2)
big_attn_mma(const float* __restrict__ bv,   // (512)
             const float* __restrict__ Wa)   // (512)
{
    extern __shared__ char dyn[];
    __shared__ float red[128 * 4];

    const int tid  = threadIdx.x;
    const int wid  = tid >> 5;
    const int lane = tid & 31;
    const int wm   = wid & 1;
    const int wn   = wid >> 1;
    const int m0   = blockIdx.y * 128;
    const int n0g  = blockIdx.x * 128;

    const uint32_t dyn_s = smem_u32(dyn);

    float acc[4][4][4] = {};

    auto prefetch = [&](int kc, int s) {
        const uint32_t as = dyn_s + s * STG_BYTES;
        const uint32_t bs = as + AS_BYTES;
        const int k0 = kc * 32;
#pragma unroll
        for (int g = 0; g < 2; g++) {
            int idx = g * 256 + tid;
            int row = idx >> 2, c = idx & 3;
            cpa16(as + row * AS_STRIDE + c * 16,
                  &g_Ah[(size_t)(m0 + row) * 1024 + k0 + c * 8]);
        }
#pragma unroll
        for (int g = 0; g < 2; g++) {
            int idx = g * 256 + tid;
            int row = idx >> 4, c = idx & 15;
            cpa16(bs + row * BS_STRIDE + c * 16,
                  &g_Bh[(size_t)(k0 + row) * 512 + n0g + c * 8]);
        }
        CP_COMMIT();
    };

    prefetch(0, 0);
    prefetch(1, 1);

    int stage = 0;
    for (int kc = 0; kc < 32; kc++) {
        if (kc < 31) { CP_WAIT(1); } else { CP_WAIT(0); }
        __syncthreads();

        if (kc < 30) {
            int ps = stage + 2; if (ps >= NSTAGE) ps -= NSTAGE;
            prefetch(kc + 2, ps);
        }

        const uint32_t as = dyn_s + stage * STG_BYTES;
        const uint32_t bs = as + AS_BYTES;

#pragma unroll
        for (int k16 = 0; k16 < 2; k16++) {
            uint32_t a_frag[4][4];
            uint32_t b_frag[4][2];
#pragma unroll
            for (int mt = 0; mt < 4; mt++) {
                int row = wm * 64 + mt * 16 + (lane & 15);
                int col = k16 * 16 + ((lane >> 4) << 3);
                ldsm_x4(a_frag[mt], as + row * AS_STRIDE + col * 2);
            }
#pragma unroll
            for (int p = 0; p < 2; p++) {
                int krow = k16 * 16 + ((lane >> 3) & 1) * 8 + (lane & 7);
                int col  = wn * 32 + p * 16 + ((lane >> 4) << 3);
                uint32_t r[4];
                ldsm_x4_t(r, bs + krow * BS_STRIDE + col * 2);
                b_frag[2 * p][0] = r[0]; b_frag[2 * p][1] = r[1];
                b_frag[2 * p + 1][0] = r[2]; b_frag[2 * p + 1][1] = r[3];
            }
#pragma unroll
            for (int mt = 0; mt < 4; mt++)
#pragma unroll
                for (int nt = 0; nt < 4; nt++)
                    mma16816(acc[mt][nt], a_frag[mt], b_frag[nt]);
        }
        stage++; if (stage >= NSTAGE) stage = 0;
    }
    __syncthreads();

    // ---- epilogue: alpha_part[m] = sum_n tanh(D + bv + hid_att) * Wa ----
    const int lane4 = lane & 3, laned4 = lane >> 2;
    float bvv[8], waa[8];
#pragma unroll
    for (int nt = 0; nt < 4; nt++) {
        int ng = n0g + wn * 32 + nt * 8 + lane4 * 2;
        bvv[2 * nt] = bv[ng];     bvv[2 * nt + 1] = bv[ng + 1];
        waa[2 * nt] = Wa[ng];     waa[2 * nt + 1] = Wa[ng + 1];
    }
#pragma unroll
    for (int mt = 0; mt < 4; mt++) {
        float srow[2] = {0.f, 0.f};
#pragma unroll
        for (int h = 0; h < 2; h++) {
            int rloc = wm * 64 + mt * 16 + laned4 + h * 8;
            int bb = (m0 + rloc) / Pz;
            const float* ha = &g_hid_att[(size_t)bb * Az + n0g];
#pragma unroll
            for (int nt = 0; nt < 4; nt++) {
                int cl = wn * 32 + nt * 8 + lane4 * 2;
                float z0 = acc[mt][nt][2 * h]     + bvv[2 * nt]     + ha[cl];
                float z1 = acc[mt][nt][2 * h + 1] + bvv[2 * nt + 1] + ha[cl + 1];
                __half2 zh = __floats2half2_rn(z0, z1);
                uint32_t th = tanh_f16x2(*(uint32_t*)&zh);
                float2 tf = __half22float2(*(__half2*)&th);
                srow[h] += tf.x * waa[2 * nt] + tf.y * waa[2 * nt + 1];
            }
        }
#pragma unroll
        for (int h = 0; h < 2; h++) {
            float s = srow[h];
            s += __shfl_xor_sync(0xffffffffu, s, 1);
            s += __shfl_xor_sync(0xffffffffu, s, 2);
            if (lane4 == 0) {
                int rloc = wm * 64 + mt * 16 + laned4 + h * 8;
                red[rloc * 4 + wn] = s;
            }
        }
    }
    __syncthreads();
    if (tid < 128) {
        float s = red[tid * 4] + red[tid * 4 + 1] + red[tid * 4 + 2] + red[tid * 4 + 3];
        g_alpha_part[(size_t)blockIdx.x * MBIG + m0 + tid] = s;
    }
}

// ------------------------------------------------------------------
// split-K=8 fp32 GEMM, single job per launch (z = 8 K-splits)
// ------------------------------------------------------------------
__global__ void gemm_splitk(const float* __restrict__ A,
                            const float* __restrict__ W,
                            float* __restrict__ part, int N)
{
    __shared__ __align__(16) float As[16][68];
    __shared__ __align__(16) float Bs[16][68];
    const int ks = blockIdx.z;
    const int tid = threadIdx.x;
    const int tx = tid & 15, ty = tid >> 4;
    const int m0 = blockIdx.y * 64, n0 = blockIdx.x * 64;
    const int kbase = ks * 128;

    const int arow = tid >> 2, acg = (tid & 3) * 4;
    const int brow = tid >> 4, bcol = (tid & 15) * 4;

    float acc[4][4] = {};

    float4 av = *(const float4*)&A[(size_t)(m0 + arow) * 1024 + kbase + acg];
    float4 bw = *(const float4*)&W[(size_t)(kbase + brow) * N + n0 + bcol];

    for (int it = 0; it < 8; it++) {
        As[acg + 0][arow] = av.x; As[acg + 1][arow] = av.y;
        As[acg + 2][arow] = av.z; As[acg + 3][arow] = av.w;
        *(float4*)&Bs[brow][bcol] = bw;
        __syncthreads();

        if (it < 7) {
            int k0 = kbase + (it + 1) * 16;
            av = *(const float4*)&A[(size_t)(m0 + arow) * 1024 + k0 + acg];
            bw = *(const float4*)&W[(size_t)(k0 + brow) * N + n0 + bcol];
        }

#pragma unroll
        for (int k = 0; k < 16; k++) {
            float4 a4 = *(const float4*)&As[k][ty * 4];
            float4 b4 = *(const float4*)&Bs[k][tx * 4];
            float a[4] = {a4.x, a4.y, a4.z, a4.w};
            float b[4] = {b4.x, b4.y, b4.z, b4.w};
#pragma unroll
            for (int i = 0; i < 4; i++)
#pragma unroll
                for (int j = 0; j < 4; j++) acc[i][j] += a[i] * b[j];
        }
        __syncthreads();
    }

    float* out = part + (size_t)ks * 256 * N;
#pragma unroll
    for (int i = 0; i < 4; i++) {
        int m = m0 + ty * 4 + i;
#pragma unroll
        for (int j = 0; j < 4; j++)
            out[(size_t)m * N + n0 + tx * 4 + j] = acc[i][j];
    }
}

// combine 8 split-K partials + bias + activation (0=none,1=relu,2=tanh)
__global__ void combine1(const float* __restrict__ part,
                         const float* __restrict__ bias,
                         float* __restrict__ o, int N, int act)
{
    const size_t e = ((size_t)blockIdx.x * 256 + threadIdx.x) * 4;
    const size_t slab = (size_t)256 * N;
    float4 s = *(const float4*)(part + e);
#pragma unroll
    for (int t = 1; t < 8; t++) {
        float4 q = *(const float4*)(part + t * slab + e);
        s.x += q.x; s.y += q.y; s.z += q.z; s.w += q.w;
    }
    const int n = (int)(e & (size_t)(N - 1));
    float4 bvec = *(const float4*)&bias[n];
    s.x += bvec.x; s.y += bvec.y; s.z += bvec.z; s.w += bvec.w;
    if (act == 1) {
        s.x = fmaxf(s.x, 0.f); s.y = fmaxf(s.y, 0.f);
        s.z = fmaxf(s.z, 0.f); s.w = fmaxf(s.w, 0.f);
    } else if (act == 2) {
        s.x = tanhf(s.x); s.y = tanhf(s.y); s.z = tanhf(s.z); s.w = tanhf(s.w);
    }
    *(float4*)(o + e) = s;
}

// ------------------------------------------------------------------
// merged softmax + context, grid (B, 2): both CTAs of a batch compute
// the identical softmax (cheap, bit-identical), each does half the
// 1024 H-columns of context -> 512 CTAs, no extra launch.
// ------------------------------------------------------------------
__global__ void softmax_context_kernel(const float* __restrict__ Wa,
                                       float* __restrict__ out_w,
                                       float* __restrict__ out_beta)
{
    const int b = blockIdx.x;
    const int half0 = blockIdx.y * 512;     // 0 or 512
    const int tid = threadIdx.x;            // 256
    __shared__ float sh[256];
    __shared__ float vals[197];
    __shared__ float ws[197];

    // sentinel logit (same reduction shape as before -> bit-identical)
    float s = 0.f;
    for (int a = tid; a < 512; a += 256)
        s += tanhf(g_sent_att[b * 512 + a] + g_hid_att[b * 512 + a]) * Wa[a];
    sh[tid] = s; __syncthreads();
    for (int off = 128; off > 0; off >>= 1) {
        if (tid < off) sh[tid] += sh[tid + off];
        __syncthreads();
    }
    float alpha_sent = sh[0];
    __syncthreads();

    float v = -INFINITY;
    if (tid < 196) {
        int m = b * 196 + tid;
        v = g_alpha_part[m] + g_alpha_part[MBIG + m] +
            g_alpha_part[2 * MBIG + m] + g_alpha_part[3 * MBIG + m];
        vals[tid] = v;
    } else if (tid == 196) {
        v = alpha_sent; vals[196] = v;
    }
    sh[tid] = v; __syncthreads();
    for (int off = 128; off > 0; off >>= 1) {
        if (tid < off) sh[tid] = fmaxf(sh[tid], sh[tid + off]);
        __syncthreads();
    }
    float mx = sh[0]; __syncthreads();

    float e = (tid < 197) ? expf(vals[tid] - mx) : 0.f;
    sh[tid] = e; __syncthreads();
    for (int off = 128; off > 0; off >>= 1) {
        if (tid < off) sh[tid] += sh[tid + off];
        __syncthreads();
    }
    float inv = 1.f / sh[0];
    if (tid < 197) {
        float w = e * inv;
        ws[tid] = w;
        if (blockIdx.y == 0) {              // single writer
            out_w[b * 197 + tid] = w;
            if (tid == 196) out_beta[b] = w;
        }
    }
    __syncthreads();

    // context: this CTA's 512 H-columns (2 per thread, fully coalesced)
    const int h0 = half0 + tid * 2;
    const __half* hb = &g_Ah[(size_t)b * Pz * 1024 + h0];
    float2 acc = make_float2(0.f, 0.f);
#pragma unroll 4
    for (int p = 0; p < Pz; p++) {
        uint32_t u = *(const uint32_t*)(hb + (size_t)p * 1024);
        float2 x = __half22float2(*(__half2*)&u);
        float wp = ws[p];
        acc.x += x.x * wp; acc.y += x.y * wp;
    }
    const int idx = b * 1024 + h0;
    float2 sa = *(const float2*)&g_sent_aff[idx];
    float2 ha = *(const float2*)&g_hid_aff[idx];
    float wl = ws[196];
    acc.x += sa.x * wl + ha.x; acc.y += sa.y * wl + ha.y;
    *(float2*)&g_ctx[idx] = acc;
}

// ------------------------------------------------------------------
extern "C" void kernel_launch(void* const* d_in, const int* in_sizes, int n_in,
                              void* d_out, int out_size)
{
    (void)in_sizes; (void)n_in; (void)out_size;
    const float* spatial   = (const float*)d_in[0];
    const float* decoder   = (const float*)d_in[1];
    const float* st        = (const float*)d_in[2];
    const float* W_sen_aff = (const float*)d_in[3];
    const float* b_sen_aff = (const float*)d_in[4];
    const float* W_sen_att = (const float*)d_in[5];
    const float* b_sen_att = (const float*)d_in[6];
    const float* W_h_aff   = (const float*)d_in[7];
    const float* b_h_aff   = (const float*)d_in[8];
    const float* W_h_att   = (const float*)d_in[9];
    const float* b_h_att   = (const float*)d_in[10];
    const float* W_v_att   = (const float*)d_in[11];
    const float* b_v_att   = (const float*)d_in[12];
    const float* W_alpha   = (const float*)d_in[13];
    // d_in[14] = b_alpha: softmax-invariant constant, dropped
    const float* W_ctx     = (const float*)d_in[15];
    const float* b_ctx     = (const float*)d_in[16];

    float* out      = (float*)d_out;
    float* out_l    = out;
    float* out_w    = out + Bz * Hz;
    float* out_beta = out + Bz * Hz + Bz * 197;

    float *sa, *ha, *st_att, *h_att, *ctx, *affp, *attp, *finp;
    cudaGetSymbolAddress((void**)&sa,     g_sent_aff);
    cudaGetSymbolAddress((void**)&ha,     g_hid_aff);
    cudaGetSymbolAddress((void**)&st_att, g_sent_att);
    cudaGetSymbolAddress((void**)&h_att,  g_hid_att);
    cudaGetSymbolAddress((void**)&ctx,    g_ctx);
    cudaGetSymbolAddress((void**)&affp,   g_aff_part);
    cudaGetSymbolAddress((void**)&attp,   g_att_part);
    cudaGetSymbolAddress((void**)&finp,   g_fin_part);

    const size_t aff_slabs = (size_t)8 * 256 * Hz;
    const size_t att_slabs = (size_t)8 * 256 * Az;
    float* affp_hid  = affp;
    float* affp_sent = affp + aff_slabs;
    float* attp_hid  = attp;
    float* attp_sent = attp + att_slabs;

    const int BIG_SMEM = NSTAGE * STG_BYTES;   // 56832
    cudaFuncSetAttribute(big_attn_mma,
                         cudaFuncAttributeMaxDynamicSharedMemorySize, BIG_SMEM);

    static cudaStream_t s2 = nullptr, s3 = nullptr;
    static cudaEvent_t ev_fork = nullptr, ev_conv = nullptr, ev_sent = nullptr;
    if (!s2) {
        cudaStreamCreateWithFlags(&s2, cudaStreamNonBlocking);
        cudaStreamCreateWithFlags(&s3, cudaStreamNonBlocking);
        cudaEventCreateWithFlags(&ev_fork, cudaEventDisableTiming);
        cudaEventCreateWithFlags(&ev_conv, cudaEventDisableTiming);
        cudaEventCreateWithFlags(&ev_sent, cudaEventDisableTiming);
    }

    // ---- fork ----
    cudaEventRecord(ev_fork, 0);
    cudaStreamWaitEvent(s2, ev_fork, 0);
    cudaStreamWaitEvent(s3, ev_fork, 0);

    // s2: conversions (run concurrently with the hidden chain on main)
    convB_kernel<<<256, 256, 0, s2>>>(W_v_att);
    convA_kernel<<<25088, 256, 0, s2>>>(spatial);
    cudaEventRecord(ev_conv, s2);

    // s3: sentinel chain (needed only by softmax)
    gemm_splitk<<<dim3(16, 4, 8), 256, 0, s3>>>(st, W_sen_aff, affp_sent, Hz);
    combine1<<<256, 256, 0, s3>>>(affp_sent, b_sen_aff, sa, Hz, 1);
    gemm_splitk<<<dim3(8, 4, 8), 256, 0, s3>>>(sa, W_sen_att, attp_sent, Az);
    combine1<<<128, 256, 0, s3>>>(attp_sent, b_sen_att, st_att, Az, 0);
    cudaEventRecord(ev_sent, s3);

    // main: hidden chain (gates the big GEMM)
    gemm_splitk<<<dim3(16, 4, 8), 256>>>(decoder, W_h_aff, affp_hid, Hz);
    combine1<<<256, 256>>>(affp_hid, b_h_aff, ha, Hz, 2);
    gemm_splitk<<<dim3(8, 4, 8), 256>>>(ha, W_h_att, attp_hid, Az);
    combine1<<<128, 256>>>(attp_hid, b_h_att, h_att, Az, 0);

    // big GEMM: single launch (one ramp + one drain)
    cudaStreamWaitEvent(0, ev_conv, 0);
    big_attn_mma<<<dim3(4, 392), 256, BIG_SMEM>>>(b_v_att, W_alpha);

    // merged softmax + context, grid (B,2) redundant-softmax
    cudaStreamWaitEvent(0, ev_sent, 0);
    softmax_context_kernel<<<dim3(Bz, 2), 256>>>(W_alpha, out_w, out_beta);

    // out_l = tanh(ctx @ W_ctx + b_ctx)
    gemm_splitk<<<dim3(16, 4, 8), 256>>>(ctx, W_ctx, finp, Hz);
    combine1<<<256, 256>>>(finp, b_ctx, out_l, Hz, 2);
}

// round 17
// speedup vs baseline: 1.0777x; 1.0179x over previous
#include <cuda_runtime.h>
#include <cuda_fp16.h>
#include <math.h>
#include <stdint.h>

#define Bz   256
#define Pz   196
#define Hz   1024
#define Az   512
#define MBIG (Bz * Pz)   // 50176 = 392 * 128

// ------------------------------------------------------------------
// device scratch (allocations forbidden)
// ------------------------------------------------------------------
__device__ float  g_sent_aff[Bz * Hz];
__device__ float  g_hid_aff [Bz * Hz];
__device__ float  g_sent_att[Bz * Az];
__device__ float  g_hid_att [Bz * Az];
__device__ float  g_alpha_part[4 * MBIG];
__device__ float  g_aff_part[2 * 8 * Bz * Hz];  // [hid | sent] split-K=8 slabs
__device__ float  g_att_part[2 * 8 * Bz * Az];
__device__ float  g_fin_part[8 * Bz * Hz];      // >= 4 slabs of 256x1024
__device__ __half g_Ah[(size_t)MBIG * Hz];      // spatial fp16 (103 MB)
__device__ __half g_Bh[Hz * Az];                // W_v_att fp16 [K][N]
__device__ __half g_ctx_hi[Bz * Hz];            // ctx hi/lo fp16
__device__ __half g_ctx_lo[Bz * Hz];
__device__ __half g_Wc_hi[Hz * Hz];             // W_ctx hi/lo fp16 [K][N]
__device__ __half g_Wc_lo[Hz * Hz];

// ------------------------------------------------------------------
__device__ __forceinline__ uint32_t smem_u32(const void* p) {
    uint32_t a;
    asm("{ .reg .u64 t; cvta.to.shared.u64 t, %1; cvt.u32.u64 %0, t; }"
        : "=r"(a) : "l"(p));
    return a;
}
__device__ __forceinline__ void cpa16(uint32_t dst, const void* src) {
    asm volatile("cp.async.cg.shared.global [%0], [%1], 16;"
                 :: "r"(dst), "l"(src) : "memory");
}
#define CP_COMMIT() asm volatile("cp.async.commit_group;" ::: "memory")
#define CP_WAIT(n)  asm volatile("cp.async.wait_group %0;" :: "n"(n) : "memory")

__device__ __forceinline__ void ldsm_x4(uint32_t* r, uint32_t addr) {
    asm volatile("ldmatrix.sync.aligned.m8n8.x4.shared.b16 {%0,%1,%2,%3}, [%4];"
                 : "=r"(r[0]), "=r"(r[1]), "=r"(r[2]), "=r"(r[3]) : "r"(addr));
}
__device__ __forceinline__ void ldsm_x4_t(uint32_t* r, uint32_t addr) {
    asm volatile("ldmatrix.sync.aligned.m8n8.x4.trans.shared.b16 {%0,%1,%2,%3}, [%4];"
                 : "=r"(r[0]), "=r"(r[1]), "=r"(r[2]), "=r"(r[3]) : "r"(addr));
}
__device__ __forceinline__ void mma16816(float* c, const uint32_t* a, const uint32_t* b) {
    asm volatile(
        "mma.sync.aligned.m16n8k16.row.col.f32.f16.f16.f32 "
        "{%0,%1,%2,%3}, {%4,%5,%6,%7}, {%8,%9}, {%0,%1,%2,%3};"
        : "+f"(c[0]), "+f"(c[1]), "+f"(c[2]), "+f"(c[3])
        : "r"(a[0]), "r"(a[1]), "r"(a[2]), "r"(a[3]), "r"(b[0]), "r"(b[1]));
}
__device__ __forceinline__ uint32_t tanh_f16x2(uint32_t x) {
    uint32_t y;
    asm("tanh.approx.f16x2 %0, %1;" : "=r"(y) : "r"(x));
    return y;
}

// ------------------------------------------------------------------
// fp32 -> fp16 conversions (streaming, full MLP)
// ------------------------------------------------------------------
__global__ void convA_kernel(const float* __restrict__ Sp) {
    size_t base = ((size_t)blockIdx.x * 256 + threadIdx.x) * 8;
    float4 x0 = *(const float4*)&Sp[base];
    float4 x1 = *(const float4*)&Sp[base + 4];
    __half2 h[4];
    h[0] = __floats2half2_rn(x0.x, x0.y);
    h[1] = __floats2half2_rn(x0.z, x0.w);
    h[2] = __floats2half2_rn(x1.x, x1.y);
    h[3] = __floats2half2_rn(x1.z, x1.w);
    *(uint4*)&g_Ah[base] = *(uint4*)h;
}
__global__ void convB_kernel(const float* __restrict__ Wv) {
    size_t base = ((size_t)blockIdx.x * 256 + threadIdx.x) * 8;
    float4 x0 = *(const float4*)&Wv[base];
    float4 x1 = *(const float4*)&Wv[base + 4];
    __half2 h[4];
    h[0] = __floats2half2_rn(x0.x, x0.y);
    h[1] = __floats2half2_rn(x0.z, x0.w);
    h[2] = __floats2half2_rn(x1.x, x1.y);
    h[3] = __floats2half2_rn(x1.z, x1.w);
    *(uint4*)&g_Bh[base] = *(uint4*)h;
}
// W_ctx (1024x1024) -> hi/lo fp16 (same [K][N] layout)
__global__ void convWctx_kernel(const float* __restrict__ W) {
    size_t base = ((size_t)blockIdx.x * 256 + threadIdx.x) * 8;
    float v[8];
    *(float4*)&v[0] = *(const float4*)&W[base];
    *(float4*)&v[4] = *(const float4*)&W[base + 4];
    __half hh[8], ll[8];
#pragma unroll
    for (int i = 0; i < 8; i++) {
        hh[i] = __float2half_rn(v[i]);
        ll[i] = __float2half_rn(v[i] - __half2float(hh[i]));
    }
    *(uint4*)&g_Wc_hi[base] = *(uint4*)hh;
    *(uint4*)&g_Wc_lo[base] = *(uint4*)ll;
}

// ------------------------------------------------------------------
// big fused attention GEMM on HMMA, BM=128 BN=128 BK=32
// 3-stage cp.async ring, single launch grid (4 chunks, 392 m-tiles).
// ------------------------------------------------------------------
#define AS_STRIDE 80
#define BS_STRIDE 272
#define AS_BYTES  10240
#define BS_BYTES  8704
#define STG_BYTES (AS_BYTES + BS_BYTES)
#define NSTAGE    3

__global__ void __launch_bounds__(256, 2)
big_attn_mma(const float* __restrict__ bv,   // (512)
             const float* __restrict__ Wa)   // (512)
{
    extern __shared__ char dyn[];
    __shared__ float red[128 * 4];

    const int tid  = threadIdx.x;
    const int wid  = tid >> 5;
    const int lane = tid & 31;
    const int wm   = wid & 1;
    const int wn   = wid >> 1;
    const int m0   = blockIdx.y * 128;
    const int n0g  = blockIdx.x * 128;

    const uint32_t dyn_s = smem_u32(dyn);

    float acc[4][4][4] = {};

    auto prefetch = [&](int kc, int s) {
        const uint32_t as = dyn_s + s * STG_BYTES;
        const uint32_t bs = as + AS_BYTES;
        const int k0 = kc * 32;
#pragma unroll
        for (int g = 0; g < 2; g++) {
            int idx = g * 256 + tid;
            int row = idx >> 2, c = idx & 3;
            cpa16(as + row * AS_STRIDE + c * 16,
                  &g_Ah[(size_t)(m0 + row) * 1024 + k0 + c * 8]);
        }
#pragma unroll
        for (int g = 0; g < 2; g++) {
            int idx = g * 256 + tid;
            int row = idx >> 4, c = idx & 15;
            cpa16(bs + row * BS_STRIDE + c * 16,
                  &g_Bh[(size_t)(k0 + row) * 512 + n0g + c * 8]);
        }
        CP_COMMIT();
    };

    prefetch(0, 0);
    prefetch(1, 1);

    int stage = 0;
    for (int kc = 0; kc < 32; kc++) {
        if (kc < 31) { CP_WAIT(1); } else { CP_WAIT(0); }
        __syncthreads();

        if (kc < 30) {
            int ps = stage + 2; if (ps >= NSTAGE) ps -= NSTAGE;
            prefetch(kc + 2, ps);
        }

        const uint32_t as = dyn_s + stage * STG_BYTES;
        const uint32_t bs = as + AS_BYTES;

#pragma unroll
        for (int k16 = 0; k16 < 2; k16++) {
            uint32_t a_frag[4][4];
            uint32_t b_frag[4][2];
#pragma unroll
            for (int mt = 0; mt < 4; mt++) {
                int row = wm * 64 + mt * 16 + (lane & 15);
                int col = k16 * 16 + ((lane >> 4) << 3);
                ldsm_x4(a_frag[mt], as + row * AS_STRIDE + col * 2);
            }
#pragma unroll
            for (int p = 0; p < 2; p++) {
                int krow = k16 * 16 + ((lane >> 3) & 1) * 8 + (lane & 7);
                int col  = wn * 32 + p * 16 + ((lane >> 4) << 3);
                uint32_t r[4];
                ldsm_x4_t(r, bs + krow * BS_STRIDE + col * 2);
                b_frag[2 * p][0] = r[0]; b_frag[2 * p][1] = r[1];
                b_frag[2 * p + 1][0] = r[2]; b_frag[2 * p + 1][1] = r[3];
            }
#pragma unroll
            for (int mt = 0; mt < 4; mt++)
#pragma unroll
                for (int nt = 0; nt < 4; nt++)
                    mma16816(acc[mt][nt], a_frag[mt], b_frag[nt]);
        }
        stage++; if (stage >= NSTAGE) stage = 0;
    }
    __syncthreads();

    // ---- epilogue: alpha_part[m] = sum_n tanh(D + bv + hid_att) * Wa ----
    const int lane4 = lane & 3, laned4 = lane >> 2;
    float bvv[8], waa[8];
#pragma unroll
    for (int nt = 0; nt < 4; nt++) {
        int ng = n0g + wn * 32 + nt * 8 + lane4 * 2;
        bvv[2 * nt] = bv[ng];     bvv[2 * nt + 1] = bv[ng + 1];
        waa[2 * nt] = Wa[ng];     waa[2 * nt + 1] = Wa[ng + 1];
    }
#pragma unroll
    for (int mt = 0; mt < 4; mt++) {
        float srow[2] = {0.f, 0.f};
#pragma unroll
        for (int h = 0; h < 2; h++) {
            int rloc = wm * 64 + mt * 16 + laned4 + h * 8;
            int bb = (m0 + rloc) / Pz;
            const float* ha = &g_hid_att[(size_t)bb * Az + n0g];
#pragma unroll
            for (int nt = 0; nt < 4; nt++) {
                int cl = wn * 32 + nt * 8 + lane4 * 2;
                float z0 = acc[mt][nt][2 * h]     + bvv[2 * nt]     + ha[cl];
                float z1 = acc[mt][nt][2 * h + 1] + bvv[2 * nt + 1] + ha[cl + 1];
                __half2 zh = __floats2half2_rn(z0, z1);
                uint32_t th = tanh_f16x2(*(uint32_t*)&zh);
                float2 tf = __half22float2(*(__half2*)&th);
                srow[h] += tf.x * waa[2 * nt] + tf.y * waa[2 * nt + 1];
            }
        }
#pragma unroll
        for (int h = 0; h < 2; h++) {
            float s = srow[h];
            s += __shfl_xor_sync(0xffffffffu, s, 1);
            s += __shfl_xor_sync(0xffffffffu, s, 2);
            if (lane4 == 0) {
                int rloc = wm * 64 + mt * 16 + laned4 + h * 8;
                red[rloc * 4 + wn] = s;
            }
        }
    }
    __syncthreads();
    if (tid < 128) {
        float s = red[tid * 4] + red[tid * 4 + 1] + red[tid * 4 + 2] + red[tid * 4 + 3];
        g_alpha_part[(size_t)blockIdx.x * MBIG + m0 + tid] = s;
    }
}

// ------------------------------------------------------------------
// split-K=8 fp32 GEMM (pre-big chains only now)
// ------------------------------------------------------------------
__global__ void gemm_splitk(const float* __restrict__ A,
                            const float* __restrict__ W,
                            float* __restrict__ part, int N)
{
    __shared__ __align__(16) float As[16][68];
    __shared__ __align__(16) float Bs[16][68];
    const int ks = blockIdx.z;
    const int tid = threadIdx.x;
    const int tx = tid & 15, ty = tid >> 4;
    const int m0 = blockIdx.y * 64, n0 = blockIdx.x * 64;
    const int kbase = ks * 128;

    const int arow = tid >> 2, acg = (tid & 3) * 4;
    const int brow = tid >> 4, bcol = (tid & 15) * 4;

    float acc[4][4] = {};

    float4 av = *(const float4*)&A[(size_t)(m0 + arow) * 1024 + kbase + acg];
    float4 bw = *(const float4*)&W[(size_t)(kbase + brow) * N + n0 + bcol];

    for (int it = 0; it < 8; it++) {
        As[acg + 0][arow] = av.x; As[acg + 1][arow] = av.y;
        As[acg + 2][arow] = av.z; As[acg + 3][arow] = av.w;
        *(float4*)&Bs[brow][bcol] = bw;
        __syncthreads();

        if (it < 7) {
            int k0 = kbase + (it + 1) * 16;
            av = *(const float4*)&A[(size_t)(m0 + arow) * 1024 + k0 + acg];
            bw = *(const float4*)&W[(size_t)(k0 + brow) * N + n0 + bcol];
        }

#pragma unroll
        for (int k = 0; k < 16; k++) {
            float4 a4 = *(const float4*)&As[k][ty * 4];
            float4 b4 = *(const float4*)&Bs[k][tx * 4];
            float a[4] = {a4.x, a4.y, a4.z, a4.w};
            float b[4] = {b4.x, b4.y, b4.z, b4.w};
#pragma unroll
            for (int i = 0; i < 4; i++)
#pragma unroll
                for (int j = 0; j < 4; j++) acc[i][j] += a[i] * b[j];
        }
        __syncthreads();
    }

    float* out = part + (size_t)ks * 256 * N;
#pragma unroll
    for (int i = 0; i < 4; i++) {
        int m = m0 + ty * 4 + i;
#pragma unroll
        for (int j = 0; j < 4; j++)
            out[(size_t)m * N + n0 + tx * 4 + j] = acc[i][j];
    }
}

// combine 8 split-K partials + bias + activation (0=none,1=relu,2=tanh)
__global__ void combine1(const float* __restrict__ part,
                         const float* __restrict__ bias,
                         float* __restrict__ o, int N, int act)
{
    const size_t e = ((size_t)blockIdx.x * 256 + threadIdx.x) * 4;
    const size_t slab = (size_t)256 * N;
    float4 s = *(const float4*)(part + e);
#pragma unroll
    for (int t = 1; t < 8; t++) {
        float4 q = *(const float4*)(part + t * slab + e);
        s.x += q.x; s.y += q.y; s.z += q.z; s.w += q.w;
    }
    const int n = (int)(e & (size_t)(N - 1));
    float4 bvec = *(const float4*)&bias[n];
    s.x += bvec.x; s.y += bvec.y; s.z += bvec.z; s.w += bvec.w;
    if (act == 1) {
        s.x = fmaxf(s.x, 0.f); s.y = fmaxf(s.y, 0.f);
        s.z = fmaxf(s.z, 0.f); s.w = fmaxf(s.w, 0.f);
    } else if (act == 2) {
        s.x = tanhf(s.x); s.y = tanhf(s.y); s.z = tanhf(s.z); s.w = tanhf(s.w);
    }
    *(float4*)(o + e) = s;
}

// ------------------------------------------------------------------
// merged softmax + context per batch (R13 shape); writes ctx as fp16 hi/lo
// ------------------------------------------------------------------
__global__ void softmax_context_kernel(const float* __restrict__ Wa,
                                       float* __restrict__ out_w,
                                       float* __restrict__ out_beta)
{
    const int b = blockIdx.x;
    const int tid = threadIdx.x;
    __shared__ float sh[256];
    __shared__ float vals[197];
    __shared__ float ws[197];

    float s = 0.f;
    for (int a = tid; a < 512; a += 256)
        s += tanhf(g_sent_att[b * 512 + a] + g_hid_att[b * 512 + a]) * Wa[a];
    sh[tid] = s; __syncthreads();
    for (int off = 128; off > 0; off >>= 1) {
        if (tid < off) sh[tid] += sh[tid + off];
        __syncthreads();
    }
    float alpha_sent = sh[0];
    __syncthreads();

    float v = -INFINITY;
    if (tid < 196) {
        int m = b * 196 + tid;
        v = g_alpha_part[m] + g_alpha_part[MBIG + m] +
            g_alpha_part[2 * MBIG + m] + g_alpha_part[3 * MBIG + m];
        vals[tid] = v;
    } else if (tid == 196) {
        v = alpha_sent; vals[196] = v;
    }
    sh[tid] = v; __syncthreads();
    for (int off = 128; off > 0; off >>= 1) {
        if (tid < off) sh[tid] = fmaxf(sh[tid], sh[tid + off]);
        __syncthreads();
    }
    float mx = sh[0]; __syncthreads();

    float e = (tid < 197) ? expf(vals[tid] - mx) : 0.f;
    sh[tid] = e; __syncthreads();
    for (int off = 128; off > 0; off >>= 1) {
        if (tid < off) sh[tid] += sh[tid + off];
        __syncthreads();
    }
    float inv = 1.f / sh[0];
    if (tid < 197) {
        float w = e * inv;
        ws[tid] = w;
        out_w[b * 197 + tid] = w;
        if (tid == 196) out_beta[b] = w;
    }
    __syncthreads();

    // context from fp16 spatial; store ctx as hi/lo fp16
    const int h0 = tid * 4;
    const __half* hb = &g_Ah[(size_t)b * Pz * 1024 + h0];
    float4 acc = make_float4(0.f, 0.f, 0.f, 0.f);
#pragma unroll 4
    for (int p = 0; p < Pz; p++) {
        uint2 u = *(const uint2*)(hb + (size_t)p * 1024);
        float2 lo = __half22float2(*(__half2*)&u.x);
        float2 hi = __half22float2(*(__half2*)&u.y);
        float wp = ws[p];
        acc.x += lo.x * wp; acc.y += lo.y * wp;
        acc.z += hi.x * wp; acc.w += hi.y * wp;
    }
    const int idx = b * 1024 + h0;
    float4 sa = *(const float4*)&g_sent_aff[idx];
    float4 ha = *(const float4*)&g_hid_aff[idx];
    float wl = ws[196];
    acc.x += sa.x * wl + ha.x; acc.y += sa.y * wl + ha.y;
    acc.z += sa.z * wl + ha.z; acc.w += sa.w * wl + ha.w;

    float v4[4] = {acc.x, acc.y, acc.z, acc.w};
    __half hh[4], ll[4];
#pragma unroll
    for (int i = 0; i < 4; i++) {
        hh[i] = __float2half_rn(v4[i]);
        ll[i] = __float2half_rn(v4[i] - __half2float(hh[i]));
    }
    *(uint2*)&g_ctx_hi[idx] = *(uint2*)hh;
    *(uint2*)&g_ctx_lo[idx] = *(uint2*)ll;
}

// ------------------------------------------------------------------
// fin_mma: out_partial = ctx(hi/lo) @ W_ctx(hi/lo), 3-pass HMMA
// BM=64 BN=64 BK=32, K-split 4. grid (16 n, 4 m, 4 ks), 256 thr.
// warps: wm = wid&1 (2x32 rows), wn = wid>>1 (4x16 cols).
// ------------------------------------------------------------------
#define FA_STRIDE 80      // 32 halves + pad
#define FB_STRIDE 144     // 64 halves + pad
#define FA_BYTES  5120    // 64*80
#define FB_BYTES  4608    // 32*144
#define FSTG (2 * FA_BYTES + 2 * FB_BYTES)   // 19456

__global__ void __launch_bounds__(256, 2)
fin_mma(float* __restrict__ part)
{
    extern __shared__ char dyn[];
    const uint32_t dyn_s = smem_u32(dyn);

    const int tid  = threadIdx.x;
    const int wid  = tid >> 5;
    const int lane = tid & 31;
    const int wm   = wid & 1;
    const int wn   = wid >> 1;
    const int n0   = blockIdx.x * 64;
    const int m0   = blockIdx.y * 64;
    const int kbase = blockIdx.z * 256;

    float acc[2][2][4] = {};

    auto prefetch = [&](int c, int s) {
        const uint32_t base = dyn_s + s * FSTG;
        const uint32_t ahi = base, alo = base + FA_BYTES;
        const uint32_t bhi = base + 2 * FA_BYTES, blo = bhi + FB_BYTES;
        const int k0 = kbase + c * 32;
        {   // A: 64 rows x 32 halves = 256 x 16B, 1 per thread
            int row = tid >> 2, cg = tid & 3;
            size_t off = (size_t)(m0 + row) * 1024 + k0 + cg * 8;
            cpa16(ahi + row * FA_STRIDE + cg * 16, &g_ctx_hi[off]);
            cpa16(alo + row * FA_STRIDE + cg * 16, &g_ctx_lo[off]);
        }
        {   // B: 32 rows x 64 halves = 256 x 16B, 1 per thread
            int row = tid >> 3, cg = tid & 7;
            size_t off = (size_t)(k0 + row) * 1024 + n0 + cg * 8;
            cpa16(bhi + row * FB_STRIDE + cg * 16, &g_Wc_hi[off]);
            cpa16(blo + row * FB_STRIDE + cg * 16, &g_Wc_lo[off]);
        }
        CP_COMMIT();
    };

    prefetch(0, 0);

    for (int c = 0; c < 8; c++) {
        const int s = c & 1;
        CP_WAIT(0);
        __syncthreads();
        if (c < 7) prefetch(c + 1, s ^ 1);

        const uint32_t base = dyn_s + s * FSTG;
        const uint32_t ahi = base, alo = base + FA_BYTES;
        const uint32_t bhi = base + 2 * FA_BYTES, blo = bhi + FB_BYTES;

#pragma unroll
        for (int k16 = 0; k16 < 2; k16++) {
            uint32_t a_hi[2][4], a_lo[2][4], b_hi[2][2], b_lo[2][2];
            const int acol = k16 * 16 + ((lane >> 4) << 3);
#pragma unroll
            for (int mt = 0; mt < 2; mt++) {
                int row = wm * 32 + mt * 16 + (lane & 15);
                ldsm_x4(a_hi[mt], ahi + row * FA_STRIDE + acol * 2);
                ldsm_x4(a_lo[mt], alo + row * FA_STRIDE + acol * 2);
            }
            {
                int krow = k16 * 16 + ((lane >> 3) & 1) * 8 + (lane & 7);
                int col  = wn * 16 + ((lane >> 4) << 3);
                uint32_t r[4];
                ldsm_x4_t(r, bhi + krow * FB_STRIDE + col * 2);
                b_hi[0][0] = r[0]; b_hi[0][1] = r[1];
                b_hi[1][0] = r[2]; b_hi[1][1] = r[3];
                ldsm_x4_t(r, blo + krow * FB_STRIDE + col * 2);
                b_lo[0][0] = r[0]; b_lo[0][1] = r[1];
                b_lo[1][0] = r[2]; b_lo[1][1] = r[3];
            }
#pragma unroll
            for (int mt = 0; mt < 2; mt++)
#pragma unroll
                for (int nt = 0; nt < 2; nt++) {
                    mma16816(acc[mt][nt], a_hi[mt], b_hi[nt]);
                    mma16816(acc[mt][nt], a_hi[mt], b_lo[nt]);
                    mma16816(acc[mt][nt], a_lo[mt], b_hi[nt]);
                }
        }
        __syncthreads();
    }

    // write fp32 partial
    const int lane4 = lane & 3, laned4 = lane >> 2;
    float* out = part + (size_t)blockIdx.z * 256 * 1024;
#pragma unroll
    for (int mt = 0; mt < 2; mt++)
#pragma unroll
        for (int h = 0; h < 2; h++) {
            int m = m0 + wm * 32 + mt * 16 + laned4 + h * 8;
            int n = n0 + wn * 16;
#pragma unroll
            for (int nt = 0; nt < 2; nt++) {
                float2 v = make_float2(acc[mt][nt][2 * h], acc[mt][nt][2 * h + 1]);
                *(float2*)&out[(size_t)m * 1024 + n + nt * 8 + lane4 * 2] = v;
            }
        }
}

// combine 4 fin partials + bias + tanh -> out_l
__global__ void combine4(const float* __restrict__ part,
                         const float* __restrict__ bias,
                         float* __restrict__ o)
{
    const size_t e = ((size_t)blockIdx.x * 256 + threadIdx.x) * 4;
    const size_t slab = (size_t)256 * 1024;
    float4 s = *(const float4*)(part + e);
#pragma unroll
    for (int t = 1; t < 4; t++) {
        float4 q = *(const float4*)(part + t * slab + e);
        s.x += q.x; s.y += q.y; s.z += q.z; s.w += q.w;
    }
    const int n = (int)(e & 1023);
    float4 bvec = *(const float4*)&bias[n];
    s.x = tanhf(s.x + bvec.x); s.y = tanhf(s.y + bvec.y);
    s.z = tanhf(s.z + bvec.z); s.w = tanhf(s.w + bvec.w);
    *(float4*)(o + e) = s;
}

// ------------------------------------------------------------------
extern "C" void kernel_launch(void* const* d_in, const int* in_sizes, int n_in,
                              void* d_out, int out_size)
{
    (void)in_sizes; (void)n_in; (void)out_size;
    const float* spatial   = (const float*)d_in[0];
    const float* decoder   = (const float*)d_in[1];
    const float* st        = (const float*)d_in[2];
    const float* W_sen_aff = (const float*)d_in[3];
    const float* b_sen_aff = (const float*)d_in[4];
    const float* W_sen_att = (const float*)d_in[5];
    const float* b_sen_att = (const float*)d_in[6];
    const float* W_h_aff   = (const float*)d_in[7];
    const float* b_h_aff   = (const float*)d_in[8];
    const float* W_h_att   = (const float*)d_in[9];
    const float* b_h_att   = (const float*)d_in[10];
    const float* W_v_att   = (const float*)d_in[11];
    const float* b_v_att   = (const float*)d_in[12];
    const float* W_alpha   = (const float*)d_in[13];
    // d_in[14] = b_alpha: softmax-invariant constant, dropped
    const float* W_ctx     = (const float*)d_in[15];
    const float* b_ctx     = (const float*)d_in[16];

    float* out      = (float*)d_out;
    float* out_l    = out;
    float* out_w    = out + Bz * Hz;
    float* out_beta = out + Bz * Hz + Bz * 197;

    float *sa, *ha, *st_att, *h_att, *affp, *attp, *finp;
    cudaGetSymbolAddress((void**)&sa,     g_sent_aff);
    cudaGetSymbolAddress((void**)&ha,     g_hid_aff);
    cudaGetSymbolAddress((void**)&st_att, g_sent_att);
    cudaGetSymbolAddress((void**)&h_att,  g_hid_att);
    cudaGetSymbolAddress((void**)&affp,   g_aff_part);
    cudaGetSymbolAddress((void**)&attp,   g_att_part);
    cudaGetSymbolAddress((void**)&finp,   g_fin_part);

    const size_t aff_slabs = (size_t)8 * 256 * Hz;
    const size_t att_slabs = (size_t)8 * 256 * Az;
    float* affp_hid  = affp;
    float* affp_sent = affp + aff_slabs;
    float* attp_hid  = attp;
    float* attp_sent = attp + att_slabs;

    const int BIG_SMEM = NSTAGE * STG_BYTES;   // 56832
    cudaFuncSetAttribute(big_attn_mma,
                         cudaFuncAttributeMaxDynamicSharedMemorySize, BIG_SMEM);
    const int FIN_SMEM = 2 * FSTG;             // 38912
    cudaFuncSetAttribute(fin_mma,
                         cudaFuncAttributeMaxDynamicSharedMemorySize, FIN_SMEM);

    static cudaStream_t s2 = nullptr, s3 = nullptr;
    static cudaEvent_t ev_fork = nullptr, ev_conv = nullptr,
                       ev_sent = nullptr, ev_wc = nullptr;
    if (!s2) {
        cudaStreamCreateWithFlags(&s2, cudaStreamNonBlocking);
        cudaStreamCreateWithFlags(&s3, cudaStreamNonBlocking);
        cudaEventCreateWithFlags(&ev_fork, cudaEventDisableTiming);
        cudaEventCreateWithFlags(&ev_conv, cudaEventDisableTiming);
        cudaEventCreateWithFlags(&ev_sent, cudaEventDisableTiming);
        cudaEventCreateWithFlags(&ev_wc, cudaEventDisableTiming);
    }

    // ---- fork ----
    cudaEventRecord(ev_fork, 0);
    cudaStreamWaitEvent(s2, ev_fork, 0);
    cudaStreamWaitEvent(s3, ev_fork, 0);

    // s2: conversions (big gate first, W_ctx conversion after)
    convB_kernel<<<256, 256, 0, s2>>>(W_v_att);
    convA_kernel<<<25088, 256, 0, s2>>>(spatial);
    cudaEventRecord(ev_conv, s2);
    convWctx_kernel<<<512, 256, 0, s2>>>(W_ctx);
    cudaEventRecord(ev_wc, s2);

    // s3: sentinel chain (needed only by softmax)
    gemm_splitk<<<dim3(16, 4, 8), 256, 0, s3>>>(st, W_sen_aff, affp_sent, Hz);
    combine1<<<256, 256, 0, s3>>>(affp_sent, b_sen_aff, sa, Hz, 1);
    gemm_splitk<<<dim3(8, 4, 8), 256, 0, s3>>>(sa, W_sen_att, attp_sent, Az);
    combine1<<<128, 256, 0, s3>>>(attp_sent, b_sen_att, st_att, Az, 0);
    cudaEventRecord(ev_sent, s3);

    // main: hidden chain (gates the big GEMM)
    gemm_splitk<<<dim3(16, 4, 8), 256>>>(decoder, W_h_aff, affp_hid, Hz);
    combine1<<<256, 256>>>(affp_hid, b_h_aff, ha, Hz, 2);
    gemm_splitk<<<dim3(8, 4, 8), 256>>>(ha, W_h_att, attp_hid, Az);
    combine1<<<128, 256>>>(attp_hid, b_h_att, h_att, Az, 0);

    // big GEMM: single launch
    cudaStreamWaitEvent(0, ev_conv, 0);
    big_attn_mma<<<dim3(4, 392), 256, BIG_SMEM>>>(b_v_att, W_alpha);

    // merged softmax + context (writes ctx hi/lo)
    cudaStreamWaitEvent(0, ev_sent, 0);
    softmax_context_kernel<<<Bz, 256>>>(W_alpha, out_w, out_beta);

    // out_l = tanh(ctx @ W_ctx + b) via hi/lo HMMA, K-split 4
    cudaStreamWaitEvent(0, ev_wc, 0);
    fin_mma<<<dim3(16, 4, 4), 256, FIN_SMEM>>>(finp);
    combine4<<<256, 256>>>(finp, b_ctx, out_l);
}